// round 10
// baseline (speedup 1.0000x reference)
#include <cuda_runtime.h>
#include <cuda_bf16.h>
#include <cstdint>
#include <cstddef>

#define NPOS 8192
#define NNEG 4096
#define DIM 64
#define MROWS 24576          // NPOS + 4*NNEG
#define XROWS 12288
#define SIMCOLS 24576
#define LRUC 1

#define BM 128
#define BN 256
#define NT_M (NPOS / BM)       // 64
#define NT_N (SIMCOLS / BN)    // 96
#define NTILES (NT_M * NT_N)   // 6144

typedef unsigned long long ull;
typedef uint32_t u32;

// ---------------- device scratch (no allocs allowed) ----------------
__device__ __align__(256) __nv_bfloat16 g_Abf[NPOS * 128];    // [row][Ah(64) | Al(64)]
__device__ __align__(256) __nv_bfloat16 g_Bbf[MROWS * 128];   // [row][Bh(64) | Bl(64)]
__device__ float g_get[NPOS * DIM];
__device__ float g_counts[NPOS];
__device__ float g_vis[NPOS];
__device__ ull   g_amax[NPOS];

// ---------------- PTX helpers ----------------
__device__ __forceinline__ u32 smem_u32(const void* p) {
    u32 a; asm("{ .reg .u64 t; cvta.to.shared.u64 t, %1; cvt.u32.u64 %0, t; }" : "=r"(a) : "l"(p));
    return a;
}
__device__ __forceinline__ void cpasync16(u32 dst, const void* src) {
    asm volatile("cp.async.cg.shared.global [%0], [%1], 16;" :: "r"(dst), "l"(src) : "memory");
}
#define CP_COMMIT()  asm volatile("cp.async.commit_group;" ::: "memory")
#define CP_WAIT(n)   asm volatile("cp.async.wait_group %0;" :: "n"(n) : "memory")

__device__ __forceinline__ void ldsm4(u32& r0, u32& r1, u32& r2, u32& r3, u32 addr) {
    asm volatile("ldmatrix.sync.aligned.m8n8.x4.shared.b16 {%0,%1,%2,%3}, [%4];"
                 : "=r"(r0), "=r"(r1), "=r"(r2), "=r"(r3) : "r"(addr));
}
__device__ __forceinline__ void mma16816(float& d0, float& d1, float& d2, float& d3,
                                         u32 a0, u32 a1, u32 a2, u32 a3, u32 b0, u32 b1) {
    asm volatile("mma.sync.aligned.m16n8k16.row.col.f32.bf16.bf16.f32 "
                 "{%0,%1,%2,%3}, {%4,%5,%6,%7}, {%8,%9}, {%0,%1,%2,%3};"
                 : "+f"(d0), "+f"(d1), "+f"(d2), "+f"(d3)
                 : "r"(a0), "r"(a1), "r"(a2), "r"(a3), "r"(b0), "r"(b1));
}
__device__ __forceinline__ u32 fkey(float v) {
    u32 u = __float_as_uint(v);
    return (u & 0x80000000u) ? ~u : (u | 0x80000000u);
}

// ---------------- split + zero scratch (fused) ----------------
__global__ void split_kernel(const float* __restrict__ x, const float* __restrict__ mem) {
    const int nA = NPOS * DIM, nTot = nA + MROWS * DIM;
    const int gs = gridDim.x * blockDim.x;
    const int t0 = blockIdx.x * blockDim.x + threadIdx.x;
    for (int i = t0; i < nTot; i += gs) {
        float v; __nv_bfloat16* base; int k;
        if (i < nA) { v = x[i];        base = g_Abf + (size_t)(i >> 6) * 128;        k = i & 63; }
        else { int j = i - nA; v = mem[j]; base = g_Bbf + (size_t)(j >> 6) * 128;    k = j & 63; }
        __nv_bfloat16 h = __float2bfloat16_rn(v);
        float r = v - __bfloat162float(h);
        base[k]      = h;
        base[64 + k] = __float2bfloat16_rn(r);
    }
    for (int j = t0; j < NPOS * DIM; j += gs) g_get[j] = 0.0f;
    for (int j = t0; j < NPOS; j += gs) { g_counts[j] = 0.0f; g_vis[j] = 0.0f; g_amax[j] = 0ull; }
}

__global__ void vis_kernel(const int* __restrict__ visible) {
    int i = blockIdx.x * blockDim.x + threadIdx.x;
    if (i < NPOS / 2) g_vis[visible[i]] = 1.0f;
}

// ---------------- persistent bf16 split-GEMM + fused argmax partials ----------------
// C = A*B^T with A=Ah+Al, B=Bh+Bl; sim = AhBh + AhBl + AlBh.
// CTA 128x256, 8 warps, warp tile 64x64, 1 CTA/SM (regs free up to 255).
// Minimal-reload mainloop: 16 ldsm.x4 per ks. Persistent CTAs; A single-buffered
// (reused across n-range), B double-buffered with cp.async prefetch.
__global__ void __launch_bounds__(256, 1)
gemm_mma(const int* __restrict__ y, float* __restrict__ C, int grid) {
    extern __shared__ char smem[];
    const u32 sb = smem_u32(smem);
    const u32 As  = sb;                 // 128 rows * 256B = 32KB
    const u32 Bs0 = sb + 32768;         // 256 rows * 256B = 64KB
    const u32 Bs1 = sb + 98304;         // 64KB
    int* ys = (int*)(smem + 163840);

    const int tid  = threadIdx.x;
    const int lane = tid & 31;
    const int w    = tid >> 5;
    const int wm   = w >> 2, wn = w & 3;       // 2 x 4 warp grid
    const int wr = wm * 64, wc = wn * 64;

    const int c  = blockIdx.x;
    const int t0 = (int)(((long long)c * NTILES) / grid);
    const int t1 = (int)(((long long)(c + 1) * NTILES) / grid);
    if (t0 >= t1) return;

    auto loadA = [&](int mt) {
#pragma unroll
        for (int h = 0; h < 2; h++)
#pragma unroll
            for (int i = 0; i < 4; i++) {       // 1024 chunks of 16B
                int idx = tid + i * 256;
                int r = idx >> 3, cc = idx & 7;
                u32 dst = As + r * 256 + (u32)(((h * 8) | ((cc ^ r) & 7)) * 16);
                cpasync16(dst, g_Abf + (size_t)(mt * BM + r) * 128 + h * 64 + cc * 8);
            }
        if (tid < BM) ys[tid] = y[mt * BM + tid];
    };
    auto loadB = [&](int nt, u32 Bbase) {
#pragma unroll
        for (int h = 0; h < 2; h++)
#pragma unroll
            for (int i = 0; i < 8; i++) {       // 2048 chunks of 16B
                int idx = tid + i * 256;
                int r = idx >> 3, cc = idx & 7;
                u32 dst = Bbase + r * 256 + (u32)(((h * 8) | ((cc ^ r) & 7)) * 16);
                cpasync16(dst, g_Bbf + (size_t)(nt * BN + r) * 128 + h * 64 + cc * 8);
            }
    };

    // prologue: tile t0 -> phase-0 buffer (Bs0)
    int cur_m = t0 / NT_N;
    loadA(cur_m);
    loadB(t0 % NT_N, Bs0);
    CP_COMMIT();

    for (int i = t0; i < t1; i++) {
        const int phase = (i - t0) & 1;
        const u32 Bcur = phase ? Bs1 : Bs0;
        const u32 Bnxt = phase ? Bs0 : Bs1;
        const int mt = i / NT_N;
        const int n0 = (i % NT_N) * BN;
        const int m0 = mt * BM;
        const bool domax = (n0 < NPOS);

        CP_WAIT(0);
        __syncthreads();

        if (mt != cur_m) {                  // rare A reload
            cur_m = mt;
            loadA(mt);
            CP_COMMIT(); CP_WAIT(0);
            __syncthreads();
        }
        if (i + 1 < t1) {                   // prefetch next B
            loadB((i + 1) % NT_N, Bnxt);
            CP_COMMIT();
        }

        float acc[4][8][4];
#pragma unroll
        for (int mi = 0; mi < 4; mi++)
#pragma unroll
            for (int ni = 0; ni < 8; ni++)
#pragma unroll
                for (int q = 0; q < 4; q++) acc[mi][ni][q] = 0.0f;

        auto a_addr = [&](int mi, int ch) -> u32 {
            int row = wr + mi * 16 + (lane & 15);
            int cc  = ch + (lane >> 4);
            return As + row * 256 + (u32)(((cc & 8) | ((cc ^ row) & 7)) * 16);
        };
        auto b_addr = [&](int j, int ch) -> u32 {
            int n  = wc + j * 16 + (lane & 7) + ((lane >> 4) << 3);
            int cc = ch + ((lane >> 3) & 1);
            return Bcur + n * 256 + (u32)(((cc & 8) | ((cc ^ n) & 7)) * 16);
        };

#pragma unroll
        for (int ks = 0; ks < 4; ks++) {
            u32 af[4][4];   // Ah, later Al
            u32 bh[4][4];   // Bh (held through pass2)
            u32 bl[4][4];   // Bl
#pragma unroll
            for (int mi = 0; mi < 4; mi++)
                ldsm4(af[mi][0], af[mi][1], af[mi][2], af[mi][3], a_addr(mi, 2 * ks));
#pragma unroll
            for (int j = 0; j < 4; j++)
                ldsm4(bh[j][0], bh[j][1], bh[j][2], bh[j][3], b_addr(j, 2 * ks));
            // pass 0: Ah * Bh
#pragma unroll
            for (int mi = 0; mi < 4; mi++)
#pragma unroll
                for (int ni = 0; ni < 8; ni++) {
                    int j = ni >> 1, o = (ni & 1) * 2;
                    mma16816(acc[mi][ni][0], acc[mi][ni][1], acc[mi][ni][2], acc[mi][ni][3],
                             af[mi][0], af[mi][1], af[mi][2], af[mi][3], bh[j][o], bh[j][o + 1]);
                }
            // pass 1: Ah * Bl
#pragma unroll
            for (int j = 0; j < 4; j++)
                ldsm4(bl[j][0], bl[j][1], bl[j][2], bl[j][3], b_addr(j, 8 + 2 * ks));
#pragma unroll
            for (int mi = 0; mi < 4; mi++)
#pragma unroll
                for (int ni = 0; ni < 8; ni++) {
                    int j = ni >> 1, o = (ni & 1) * 2;
                    mma16816(acc[mi][ni][0], acc[mi][ni][1], acc[mi][ni][2], acc[mi][ni][3],
                             af[mi][0], af[mi][1], af[mi][2], af[mi][3], bl[j][o], bl[j][o + 1]);
                }
            // pass 2: Al * Bh  (af <- Al, af dead after pass1)
#pragma unroll
            for (int mi = 0; mi < 4; mi++)
                ldsm4(af[mi][0], af[mi][1], af[mi][2], af[mi][3], a_addr(mi, 8 + 2 * ks));
#pragma unroll
            for (int mi = 0; mi < 4; mi++)
#pragma unroll
                for (int ni = 0; ni < 8; ni++) {
                    int j = ni >> 1, o = (ni & 1) * 2;
                    mma16816(acc[mi][ni][0], acc[mi][ni][1], acc[mi][ni][2], acc[mi][ni][3],
                             af[mi][0], af[mi][1], af[mi][2], af[mi][3], bh[j][o], bh[j][o + 1]);
                }
        }

        // ---- epilogue: stores + fused per-row argmax partials ----
#pragma unroll
        for (int mi = 0; mi < 4; mi++) {
            int lr = wr + mi * 16 + (lane >> 2);
            float* p0 = C + (size_t)(m0 + lr) * SIMCOLS + n0 + wc + (lane & 3) * 2;
            float* p1 = p0 + (size_t)8 * SIMCOLS;
            ull k0 = 0, k1 = 0;
            int yv0 = -1, yv1 = -1;
            if (domax) { yv0 = ys[lr]; yv1 = ys[lr + 8]; }
#pragma unroll
            for (int ni = 0; ni < 8; ni++) {
                float c0 = acc[mi][ni][0], c1 = acc[mi][ni][1];
                float c2 = acc[mi][ni][2], c3 = acc[mi][ni][3];
                *(float2*)(p0 + ni * 8) = make_float2(c0, c1);
                *(float2*)(p1 + ni * 8) = make_float2(c2, c3);
                if (domax) {
                    int col = n0 + wc + ni * 8 + (lane & 3) * 2;
                    float v0 = c0 + (col     == yv0 ? 2.0f : 0.0f);
                    float v1 = c1 + (col + 1 == yv0 ? 2.0f : 0.0f);
                    float v2 = c2 + (col     == yv1 ? 2.0f : 0.0f);
                    float v3 = c3 + (col + 1 == yv1 ? 2.0f : 0.0f);
                    ull q;
                    q = ((ull)fkey(v0) << 32) | (u32)(0xFFFFFFFFu - (u32)col);       if (q > k0) k0 = q;
                    q = ((ull)fkey(v1) << 32) | (u32)(0xFFFFFFFFu - (u32)(col + 1)); if (q > k0) k0 = q;
                    q = ((ull)fkey(v2) << 32) | (u32)(0xFFFFFFFFu - (u32)col);       if (q > k1) k1 = q;
                    q = ((ull)fkey(v3) << 32) | (u32)(0xFFFFFFFFu - (u32)(col + 1)); if (q > k1) k1 = q;
                }
            }
            if (domax) {
#pragma unroll
                for (int o2 = 1; o2 <= 2; o2 <<= 1) {
                    ull t0v = __shfl_xor_sync(0xffffffffu, k0, o2); if (t0v > k0) k0 = t0v;
                    ull t1v = __shfl_xor_sync(0xffffffffu, k1, o2); if (t1v > k1) k1 = t1v;
                }
                if ((lane & 3) == 0) {
                    atomicMax(&g_amax[m0 + lr], k0);
                    atomicMax(&g_amax[m0 + lr + 8], k1);
                }
            }
        }
    }
}

// ---------------- finalize argmax + segment sums (fused) ----------------
__global__ void segsum_kernel(const float* __restrict__ x, float* __restrict__ out_y) {
    int i = blockIdx.x;          // source row
    int t = threadIdx.x;         // 0..63
    ull k = g_amax[i];
    int idx = (int)(0xFFFFFFFFu - (u32)(k & 0xFFFFFFFFull));
    if (t == 0) { out_y[i] = (float)idx; atomicAdd(&g_counts[idx], 1.0f); }
    atomicAdd(&g_get[idx * DIM + t], x[(size_t)i * DIM + t]);
}

// ---------------- memory update + normalize + slot writes ----------------
__global__ void update_kernel(const float* __restrict__ x, const float* __restrict__ memory,
                              const float* __restrict__ params, float* __restrict__ outm) {
    int r = blockIdx.x;
    int t = threadIdx.x;
    if (r < NPOS) {
        float mom   = params[3];
        float cnt   = g_counts[r];
        float valid = (cnt > 0.1f ? 1.0f : 0.0f) * g_vis[r];
        float msc   = valid * mom + 1.0f - valid;
        float gsc   = (1.0f - mom) * valid;
        float denom = cnt + 1e-8f;
        float v0 = memory[(size_t)r * DIM + t]      * msc + (g_get[r * DIM + t]      / denom) * gsc;
        float v1 = memory[(size_t)r * DIM + t + 32] * msc + (g_get[r * DIM + t + 32] / denom) * gsc;
        float ss = v0 * v0 + v1 * v1;
#pragma unroll
        for (int o = 16; o; o >>= 1) ss += __shfl_xor_sync(0xffffffffu, ss, o);
        float inv = 1.0f / fmaxf(sqrtf(ss), 1e-12f);
        outm[(size_t)r * DIM + t]      = v0 * inv;
        outm[(size_t)r * DIM + t + 32] = v1 * inv;
    } else if (r >= NPOS + LRUC * NNEG && r < NPOS + LRUC * NNEG + NNEG) {
        int xs = NPOS + (r - (NPOS + LRUC * NNEG));
        outm[(size_t)r * DIM + t]      = x[(size_t)xs * DIM + t];
        outm[(size_t)r * DIM + t + 32] = x[(size_t)xs * DIM + t + 32];
    } else {
        outm[(size_t)r * DIM + t]      = memory[(size_t)r * DIM + t];
        outm[(size_t)r * DIM + t + 32] = memory[(size_t)r * DIM + t + 32];
    }
}

// ---------------- launch ----------------
extern "C" void kernel_launch(void* const* d_in, const int* in_sizes, int n_in,
                              void* d_out, int out_size) {
    const float* x = nullptr;
    const int*   y = nullptr;
    const int*   visible = nullptr;
    const float* memory = nullptr;
    const float* params = nullptr;
    for (int i = 0; i < n_in; i++) {
        switch (in_sizes[i]) {
            case XROWS * DIM: x = (const float*)d_in[i]; break;
            case NPOS:        y = (const int*)d_in[i]; break;
            case NPOS / 2:    visible = (const int*)d_in[i]; break;
            case MROWS * DIM: memory = (const float*)d_in[i]; break;
            case 4:           params = (const float*)d_in[i]; break;
            default: break;
        }
    }

    float* sim     = (float*)d_out;
    float* out_y   = sim + (size_t)NPOS * SIMCOLS;
    float* out_mem = out_y + NPOS;

    int nsm = 148;
    cudaDeviceGetAttribute(&nsm, cudaDevAttrMultiProcessorCount, 0);

    const int SMEM_TOTAL = 163840 + 512;  // A(32K) + B0(64K) + B1(64K) + ys
    cudaFuncSetAttribute(gemm_mma, cudaFuncAttributeMaxDynamicSharedMemorySize, SMEM_TOTAL);

    split_kernel<<<2048, 256>>>(x, memory);
    vis_kernel<<<(NPOS / 2 + 255) / 256, 256>>>(visible);
    gemm_mma<<<nsm, 256, SMEM_TOTAL>>>(y, sim, nsm);
    segsum_kernel<<<NPOS, 64>>>(x, out_y);
    update_kernel<<<MROWS, 32>>>(x, memory, params, out_mem);
}

// round 12
// speedup vs baseline: 1.1077x; 1.1077x over previous
#include <cuda_runtime.h>
#include <cuda_bf16.h>
#include <cstdint>
#include <cstddef>

#define NPOS 8192
#define NNEG 4096
#define DIM 64
#define MROWS 24576          // NPOS + 4*NNEG
#define XROWS 12288
#define SIMCOLS 24576
#define LRUC 1

#define BM 128
#define BN 128
#define THREADS 128

typedef unsigned long long ull;
typedef uint32_t u32;

// ---------------- device scratch (no allocs allowed) ----------------
__device__ __align__(256) __nv_bfloat16 g_Abf[NPOS * 128];    // [row][Ah(64) | Al(64)]
__device__ __align__(256) __nv_bfloat16 g_Bbf[MROWS * 128];   // [row][Bh(64) | Bl(64)]
__device__ float g_get[NPOS * DIM];
__device__ float g_counts[NPOS];
__device__ float g_vis[NPOS];
__device__ ull   g_amax[NPOS];

// ---------------- PTX helpers ----------------
__device__ __forceinline__ u32 smem_u32(const void* p) {
    u32 a; asm("{ .reg .u64 t; cvta.to.shared.u64 t, %1; cvt.u32.u64 %0, t; }" : "=r"(a) : "l"(p));
    return a;
}
__device__ __forceinline__ void cpasync16(u32 dst, const void* src) {
    asm volatile("cp.async.cg.shared.global [%0], [%1], 16;" :: "r"(dst), "l"(src) : "memory");
}
#define CP_COMMIT()  asm volatile("cp.async.commit_group;" ::: "memory")
#define CP_WAIT(n)   asm volatile("cp.async.wait_group %0;" :: "n"(n) : "memory")

__device__ __forceinline__ void ldsm4(u32& r0, u32& r1, u32& r2, u32& r3, u32 addr) {
    asm volatile("ldmatrix.sync.aligned.m8n8.x4.shared.b16 {%0,%1,%2,%3}, [%4];"
                 : "=r"(r0), "=r"(r1), "=r"(r2), "=r"(r3) : "r"(addr));
}
__device__ __forceinline__ void mma16816(float& d0, float& d1, float& d2, float& d3,
                                         u32 a0, u32 a1, u32 a2, u32 a3, u32 b0, u32 b1) {
    asm volatile("mma.sync.aligned.m16n8k16.row.col.f32.bf16.bf16.f32 "
                 "{%0,%1,%2,%3}, {%4,%5,%6,%7}, {%8,%9}, {%0,%1,%2,%3};"
                 : "+f"(d0), "+f"(d1), "+f"(d2), "+f"(d3)
                 : "r"(a0), "r"(a1), "r"(a2), "r"(a3), "r"(b0), "r"(b1));
}
__device__ __forceinline__ u32 fkey(float v) {
    u32 u = __float_as_uint(v);
    return (u & 0x80000000u) ? ~u : (u | 0x80000000u);
}

// ---------------- split + zero scratch (fused) ----------------
__global__ void split_kernel(const float* __restrict__ x, const float* __restrict__ mem) {
    const int nA = NPOS * DIM, nTot = nA + MROWS * DIM;
    const int gs = gridDim.x * blockDim.x;
    const int t0 = blockIdx.x * blockDim.x + threadIdx.x;
    for (int i = t0; i < nTot; i += gs) {
        float v; __nv_bfloat16* base; int k;
        if (i < nA) { v = x[i];        base = g_Abf + (size_t)(i >> 6) * 128;        k = i & 63; }
        else { int j = i - nA; v = mem[j]; base = g_Bbf + (size_t)(j >> 6) * 128;    k = j & 63; }
        __nv_bfloat16 h = __float2bfloat16_rn(v);
        float r = v - __bfloat162float(h);
        base[k]      = h;
        base[64 + k] = __float2bfloat16_rn(r);
    }
    for (int j = t0; j < NPOS * DIM; j += gs) g_get[j] = 0.0f;
    for (int j = t0; j < NPOS; j += gs) { g_counts[j] = 0.0f; g_vis[j] = 0.0f; g_amax[j] = 0ull; }
}

__global__ void vis_kernel(const int* __restrict__ visible) {
    int i = blockIdx.x * blockDim.x + threadIdx.x;
    if (i < NPOS / 2) g_vis[visible[i]] = 1.0f;
}

// ---------------- bf16 split-GEMM via mma.sync + fused argmax partials ----------------
// C = A*B^T with A=Ah+Al, B=Bh+Bl; sim = AhBh + AhBl + AlBh.
// CTA 128x128 with ONLY 128 threads (4 warps, 2x2 grid, warp tile 64x64),
// 2 CTAs/SM: full register budget (no 128-reg cap) AND cross-CTA overlap.
// Per ks: 16 ldsm.x4 (minimal-reload), 96 HMMA.
__global__ void __launch_bounds__(THREADS, 2)
gemm_mma(const int* __restrict__ y, float* __restrict__ C) {
    extern __shared__ char smem[];
    const u32 sb = smem_u32(smem);
    const u32 As = sb;             // 128 rows * 256B = 32KB
    const u32 Bs = sb + 32768;     // 128 rows * 256B = 32KB
    int* ys = (int*)(smem + 65536);

    const int tid  = threadIdx.x;
    const int lane = tid & 31;
    const int w    = tid >> 5;
    const int wm   = w >> 1, wn = w & 1;       // 2x2 warp grid
    const int wr = wm * 64, wc = wn * 64;
    const int m0   = blockIdx.y * BM;
    const int n0   = blockIdx.x * BN;
    const bool domax = (n0 < NPOS);

    // ---- cp.async loads: 2048 16B-chunks each for A and B (128 threads x 16) ----
#pragma unroll
    for (int h = 0; h < 2; h++)
#pragma unroll
        for (int i = 0; i < 8; i++) {
            int idx = tid + i * THREADS;           // 0..1023 per h
            int r = idx >> 3, c = idx & 7;         // r: 0..127
            u32 dst = As + r * 256 + (u32)(((h * 8) | ((c ^ r) & 7)) * 16);
            cpasync16(dst, g_Abf + (size_t)(m0 + r) * 128 + h * 64 + c * 8);
        }
#pragma unroll
    for (int h = 0; h < 2; h++)
#pragma unroll
        for (int i = 0; i < 8; i++) {
            int idx = tid + i * THREADS;
            int r = idx >> 3, c = idx & 7;
            u32 dst = Bs + r * 256 + (u32)(((h * 8) | ((c ^ r) & 7)) * 16);
            cpasync16(dst, g_Bbf + (size_t)(n0 + r) * 128 + h * 64 + c * 8);
        }
    CP_COMMIT();
    if (domax) ys[tid] = y[m0 + tid];

    float acc[4][8][4];
#pragma unroll
    for (int mi = 0; mi < 4; mi++)
#pragma unroll
        for (int ni = 0; ni < 8; ni++)
#pragma unroll
            for (int q = 0; q < 4; q++) acc[mi][ni][q] = 0.0f;

    auto a_addr = [&](int mi, int ch) -> u32 {
        int row = wr + mi * 16 + (lane & 15);
        int cc  = ch + (lane >> 4);
        return As + row * 256 + (u32)(((cc & 8) | ((cc ^ row) & 7)) * 16);
    };
    auto b_addr = [&](int j, int ch) -> u32 {
        int n  = wc + j * 16 + (lane & 7) + ((lane >> 4) << 3);
        int cc = ch + ((lane >> 3) & 1);
        return Bs + n * 256 + (u32)(((cc & 8) | ((cc ^ n) & 7)) * 16);
    };

    CP_WAIT(0);
    __syncthreads();

#pragma unroll
    for (int ks = 0; ks < 4; ks++) {
        u32 af[4][4];   // Ah, later Al
        u32 bh[4][4];   // Bh (held through pass2)
        u32 bl[4][4];   // Bl
#pragma unroll
        for (int mi = 0; mi < 4; mi++)
            ldsm4(af[mi][0], af[mi][1], af[mi][2], af[mi][3], a_addr(mi, 2 * ks));
#pragma unroll
        for (int j = 0; j < 4; j++)
            ldsm4(bh[j][0], bh[j][1], bh[j][2], bh[j][3], b_addr(j, 2 * ks));
        // pass 0: Ah * Bh
#pragma unroll
        for (int mi = 0; mi < 4; mi++)
#pragma unroll
            for (int ni = 0; ni < 8; ni++) {
                int j = ni >> 1, o = (ni & 1) * 2;
                mma16816(acc[mi][ni][0], acc[mi][ni][1], acc[mi][ni][2], acc[mi][ni][3],
                         af[mi][0], af[mi][1], af[mi][2], af[mi][3], bh[j][o], bh[j][o + 1]);
            }
        // pass 1: Ah * Bl
#pragma unroll
        for (int j = 0; j < 4; j++)
            ldsm4(bl[j][0], bl[j][1], bl[j][2], bl[j][3], b_addr(j, 8 + 2 * ks));
#pragma unroll
        for (int mi = 0; mi < 4; mi++)
#pragma unroll
            for (int ni = 0; ni < 8; ni++) {
                int j = ni >> 1, o = (ni & 1) * 2;
                mma16816(acc[mi][ni][0], acc[mi][ni][1], acc[mi][ni][2], acc[mi][ni][3],
                         af[mi][0], af[mi][1], af[mi][2], af[mi][3], bl[j][o], bl[j][o + 1]);
            }
        // pass 2: Al * Bh  (af <- Al; af dead after pass1)
#pragma unroll
        for (int mi = 0; mi < 4; mi++)
            ldsm4(af[mi][0], af[mi][1], af[mi][2], af[mi][3], a_addr(mi, 8 + 2 * ks));
#pragma unroll
        for (int mi = 0; mi < 4; mi++)
#pragma unroll
            for (int ni = 0; ni < 8; ni++) {
                int j = ni >> 1, o = (ni & 1) * 2;
                mma16816(acc[mi][ni][0], acc[mi][ni][1], acc[mi][ni][2], acc[mi][ni][3],
                         af[mi][0], af[mi][1], af[mi][2], af[mi][3], bh[j][o], bh[j][o + 1]);
            }
    }

    // ---- epilogue: stores + fused per-row argmax partials ----
#pragma unroll
    for (int mi = 0; mi < 4; mi++) {
        int lr = wr + mi * 16 + (lane >> 2);
        float* p0 = C + (size_t)(m0 + lr) * SIMCOLS + n0 + wc + (lane & 3) * 2;
        float* p1 = p0 + (size_t)8 * SIMCOLS;
        ull k0 = 0, k1 = 0;
        int yv0 = -1, yv1 = -1;
        if (domax) { yv0 = ys[lr]; yv1 = ys[lr + 8]; }
#pragma unroll
        for (int ni = 0; ni < 8; ni++) {
            float c0 = acc[mi][ni][0], c1 = acc[mi][ni][1];
            float c2 = acc[mi][ni][2], c3 = acc[mi][ni][3];
            *(float2*)(p0 + ni * 8) = make_float2(c0, c1);
            *(float2*)(p1 + ni * 8) = make_float2(c2, c3);
            if (domax) {
                int col = n0 + wc + ni * 8 + (lane & 3) * 2;
                float v0 = c0 + (col     == yv0 ? 2.0f : 0.0f);
                float v1 = c1 + (col + 1 == yv0 ? 2.0f : 0.0f);
                float v2 = c2 + (col     == yv1 ? 2.0f : 0.0f);
                float v3 = c3 + (col + 1 == yv1 ? 2.0f : 0.0f);
                ull q;
                q = ((ull)fkey(v0) << 32) | (u32)(0xFFFFFFFFu - (u32)col);       if (q > k0) k0 = q;
                q = ((ull)fkey(v1) << 32) | (u32)(0xFFFFFFFFu - (u32)(col + 1)); if (q > k0) k0 = q;
                q = ((ull)fkey(v2) << 32) | (u32)(0xFFFFFFFFu - (u32)col);       if (q > k1) k1 = q;
                q = ((ull)fkey(v3) << 32) | (u32)(0xFFFFFFFFu - (u32)(col + 1)); if (q > k1) k1 = q;
            }
        }
        if (domax) {
#pragma unroll
            for (int o2 = 1; o2 <= 2; o2 <<= 1) {
                ull t0 = __shfl_xor_sync(0xffffffffu, k0, o2); if (t0 > k0) k0 = t0;
                ull t1 = __shfl_xor_sync(0xffffffffu, k1, o2); if (t1 > k1) k1 = t1;
            }
            if ((lane & 3) == 0) {
                atomicMax(&g_amax[m0 + lr], k0);
                atomicMax(&g_amax[m0 + lr + 8], k1);
            }
        }
    }
}

// ---------------- finalize argmax + segment sums (fused) ----------------
__global__ void segsum_kernel(const float* __restrict__ x, float* __restrict__ out_y) {
    int i = blockIdx.x;          // source row
    int t = threadIdx.x;         // 0..63
    ull k = g_amax[i];
    int idx = (int)(0xFFFFFFFFu - (u32)(k & 0xFFFFFFFFull));
    if (t == 0) { out_y[i] = (float)idx; atomicAdd(&g_counts[idx], 1.0f); }
    atomicAdd(&g_get[idx * DIM + t], x[(size_t)i * DIM + t]);
}

// ---------------- memory update + normalize + slot writes ----------------
__global__ void update_kernel(const float* __restrict__ x, const float* __restrict__ memory,
                              const float* __restrict__ params, float* __restrict__ outm) {
    int r = blockIdx.x;
    int t = threadIdx.x;
    if (r < NPOS) {
        float mom   = params[3];
        float cnt   = g_counts[r];
        float valid = (cnt > 0.1f ? 1.0f : 0.0f) * g_vis[r];
        float msc   = valid * mom + 1.0f - valid;
        float gsc   = (1.0f - mom) * valid;
        float denom = cnt + 1e-8f;
        float v0 = memory[(size_t)r * DIM + t]      * msc + (g_get[r * DIM + t]      / denom) * gsc;
        float v1 = memory[(size_t)r * DIM + t + 32] * msc + (g_get[r * DIM + t + 32] / denom) * gsc;
        float ss = v0 * v0 + v1 * v1;
#pragma unroll
        for (int o = 16; o; o >>= 1) ss += __shfl_xor_sync(0xffffffffu, ss, o);
        float inv = 1.0f / fmaxf(sqrtf(ss), 1e-12f);
        outm[(size_t)r * DIM + t]      = v0 * inv;
        outm[(size_t)r * DIM + t + 32] = v1 * inv;
    } else if (r >= NPOS + LRUC * NNEG && r < NPOS + LRUC * NNEG + NNEG) {
        int xs = NPOS + (r - (NPOS + LRUC * NNEG));
        outm[(size_t)r * DIM + t]      = x[(size_t)xs * DIM + t];
        outm[(size_t)r * DIM + t + 32] = x[(size_t)xs * DIM + t + 32];
    } else {
        outm[(size_t)r * DIM + t]      = memory[(size_t)r * DIM + t];
        outm[(size_t)r * DIM + t + 32] = memory[(size_t)r * DIM + t + 32];
    }
}

// ---------------- launch ----------------
extern "C" void kernel_launch(void* const* d_in, const int* in_sizes, int n_in,
                              void* d_out, int out_size) {
    const float* x = nullptr;
    const int*   y = nullptr;
    const int*   visible = nullptr;
    const float* memory = nullptr;
    const float* params = nullptr;
    for (int i = 0; i < n_in; i++) {
        switch (in_sizes[i]) {
            case XROWS * DIM: x = (const float*)d_in[i]; break;
            case NPOS:        y = (const int*)d_in[i]; break;
            case NPOS / 2:    visible = (const int*)d_in[i]; break;
            case MROWS * DIM: memory = (const float*)d_in[i]; break;
            case 4:           params = (const float*)d_in[i]; break;
            default: break;
        }
    }

    float* sim     = (float*)d_out;
    float* out_y   = sim + (size_t)NPOS * SIMCOLS;
    float* out_mem = out_y + NPOS;

    const int SMEM_TOTAL = 65536 + 512;   // A(32K) + B(32K) + ys
    cudaFuncSetAttribute(gemm_mma, cudaFuncAttributeMaxDynamicSharedMemorySize, SMEM_TOTAL);

    split_kernel<<<2048, 256>>>(x, memory);
    vis_kernel<<<(NPOS / 2 + 255) / 256, 256>>>(visible);
    gemm_mma<<<dim3(SIMCOLS / BN, NPOS / BM), THREADS, SMEM_TOTAL>>>(y, sim);
    segsum_kernel<<<NPOS, 64>>>(x, out_y);
    update_kernel<<<MROWS, 32>>>(x, memory, params, out_mem);
}

// round 13
// speedup vs baseline: 1.1954x; 1.0792x over previous
#include <cuda_runtime.h>
#include <cuda_bf16.h>
#include <cstdint>
#include <cstddef>

#define NPOS 8192
#define NNEG 4096
#define DIM 64
#define MROWS 24576          // NPOS + 4*NNEG
#define XROWS 12288
#define SIMCOLS 24576
#define LRUC 1

#define BM 128
#define BN 64
#define THREADS 128

typedef unsigned long long ull;
typedef uint32_t u32;

// ---------------- device scratch (no allocs allowed) ----------------
__device__ __align__(256) __nv_bfloat16 g_Abf[NPOS * 128];    // [row][Ah(64) | Al(64)]
__device__ __align__(256) __nv_bfloat16 g_Bbf[MROWS * 128];   // [row][Bh(64) | Bl(64)]
__device__ float g_get[NPOS * DIM];
__device__ float g_counts[NPOS];
__device__ float g_vis[NPOS];
__device__ ull   g_amax[NPOS];

// ---------------- PTX helpers ----------------
__device__ __forceinline__ u32 smem_u32(const void* p) {
    u32 a; asm("{ .reg .u64 t; cvta.to.shared.u64 t, %1; cvt.u32.u64 %0, t; }" : "=r"(a) : "l"(p));
    return a;
}
__device__ __forceinline__ void cpasync16(u32 dst, const void* src) {
    asm volatile("cp.async.cg.shared.global [%0], [%1], 16;" :: "r"(dst), "l"(src) : "memory");
}
#define CP_COMMIT()  asm volatile("cp.async.commit_group;" ::: "memory")
#define CP_WAIT(n)   asm volatile("cp.async.wait_group %0;" :: "n"(n) : "memory")

__device__ __forceinline__ void ldsm4(u32& r0, u32& r1, u32& r2, u32& r3, u32 addr) {
    asm volatile("ldmatrix.sync.aligned.m8n8.x4.shared.b16 {%0,%1,%2,%3}, [%4];"
                 : "=r"(r0), "=r"(r1), "=r"(r2), "=r"(r3) : "r"(addr));
}
__device__ __forceinline__ void mma16816(float& d0, float& d1, float& d2, float& d3,
                                         u32 a0, u32 a1, u32 a2, u32 a3, u32 b0, u32 b1) {
    asm volatile("mma.sync.aligned.m16n8k16.row.col.f32.bf16.bf16.f32 "
                 "{%0,%1,%2,%3}, {%4,%5,%6,%7}, {%8,%9}, {%0,%1,%2,%3};"
                 : "+f"(d0), "+f"(d1), "+f"(d2), "+f"(d3)
                 : "r"(a0), "r"(a1), "r"(a2), "r"(a3), "r"(b0), "r"(b1));
}
__device__ __forceinline__ u32 fkey(float v) {
    u32 u = __float_as_uint(v);
    return (u & 0x80000000u) ? ~u : (u | 0x80000000u);
}

// ---------------- split + zero scratch (fused) ----------------
__global__ void split_kernel(const float* __restrict__ x, const float* __restrict__ mem) {
    const int nA = NPOS * DIM, nTot = nA + MROWS * DIM;
    const int gs = gridDim.x * blockDim.x;
    const int t0 = blockIdx.x * blockDim.x + threadIdx.x;
    for (int i = t0; i < nTot; i += gs) {
        float v; __nv_bfloat16* base; int k;
        if (i < nA) { v = x[i];        base = g_Abf + (size_t)(i >> 6) * 128;        k = i & 63; }
        else { int j = i - nA; v = mem[j]; base = g_Bbf + (size_t)(j >> 6) * 128;    k = j & 63; }
        __nv_bfloat16 h = __float2bfloat16_rn(v);
        float r = v - __bfloat162float(h);
        base[k]      = h;
        base[64 + k] = __float2bfloat16_rn(r);
    }
    for (int j = t0; j < NPOS * DIM; j += gs) g_get[j] = 0.0f;
    for (int j = t0; j < NPOS; j += gs) { g_counts[j] = 0.0f; g_vis[j] = 0.0f; g_amax[j] = 0ull; }
}

__global__ void vis_kernel(const int* __restrict__ visible) {
    int i = blockIdx.x * blockDim.x + threadIdx.x;
    if (i < NPOS / 2) g_vis[visible[i]] = 1.0f;
}

// ---------------- bf16 split-GEMM via mma.sync + fused argmax partials ----------------
// C = A*B^T with A=Ah+Al, B=Bh+Bl; sim = AhBh + AhBl + AlBh.
// CTA tile 128x64, 128 threads (4 warps, 2x2 grid, warp tile 64x32), 4 CTAs/SM:
// 4 independent barrier domains per SM so load/epilogue phases interleave
// across CTAs and keep the tensor pipe fed. ~124 regs (fits 4x128 threads).
__global__ void __launch_bounds__(THREADS, 4)
gemm_mma(const int* __restrict__ y, float* __restrict__ C) {
    extern __shared__ char smem[];
    const u32 sb = smem_u32(smem);
    const u32 As = sb;             // 128 rows * 256B = 32KB
    const u32 Bs = sb + 32768;     // 64 rows * 256B = 16KB
    int* ys = (int*)(smem + 49152);

    const int tid  = threadIdx.x;
    const int lane = tid & 31;
    const int w    = tid >> 5;
    const int wm   = w >> 1, wn = w & 1;       // 2x2 warp grid
    const int wr = wm * 64, wc = wn * 32;
    const int m0   = blockIdx.y * BM;
    const int n0   = blockIdx.x * BN;
    const bool domax = (n0 < NPOS);

    // ---- cp.async loads: A 2048 chunks (16 iters), B 1024 chunks (8 iters) ----
#pragma unroll
    for (int h = 0; h < 2; h++)
#pragma unroll
        for (int i = 0; i < 8; i++) {
            int idx = tid + i * THREADS;           // 0..1023 per h
            int r = idx >> 3, c = idx & 7;         // r: 0..127
            u32 dst = As + r * 256 + (u32)(((h * 8) | ((c ^ r) & 7)) * 16);
            cpasync16(dst, g_Abf + (size_t)(m0 + r) * 128 + h * 64 + c * 8);
        }
#pragma unroll
    for (int h = 0; h < 2; h++)
#pragma unroll
        for (int i = 0; i < 4; i++) {
            int idx = tid + i * THREADS;           // 0..511 per h
            int r = idx >> 3, c = idx & 7;         // r: 0..63
            u32 dst = Bs + r * 256 + (u32)(((h * 8) | ((c ^ r) & 7)) * 16);
            cpasync16(dst, g_Bbf + (size_t)(n0 + r) * 128 + h * 64 + c * 8);
        }
    CP_COMMIT();
    if (domax) ys[tid] = y[m0 + tid];

    float acc[4][4][4];
#pragma unroll
    for (int mi = 0; mi < 4; mi++)
#pragma unroll
        for (int ni = 0; ni < 4; ni++)
#pragma unroll
            for (int q = 0; q < 4; q++) acc[mi][ni][q] = 0.0f;

    auto a_addr = [&](int mi, int ch) -> u32 {
        int row = wr + mi * 16 + (lane & 15);
        int cc  = ch + (lane >> 4);
        return As + row * 256 + (u32)(((cc & 8) | ((cc ^ row) & 7)) * 16);
    };
    auto b_addr = [&](int j, int ch) -> u32 {
        int n  = wc + j * 16 + (lane & 7) + ((lane >> 4) << 3);
        int cc = ch + ((lane >> 3) & 1);
        return Bs + n * 256 + (u32)(((cc & 8) | ((cc ^ n) & 7)) * 16);
    };

    CP_WAIT(0);
    __syncthreads();

#pragma unroll
    for (int ks = 0; ks < 4; ks++) {
        u32 af[4][4];   // Ah, later Al
        u32 bh[2][4];   // Bh (held through pass2)
        u32 bl[2][4];   // Bl
#pragma unroll
        for (int mi = 0; mi < 4; mi++)
            ldsm4(af[mi][0], af[mi][1], af[mi][2], af[mi][3], a_addr(mi, 2 * ks));
#pragma unroll
        for (int j = 0; j < 2; j++)
            ldsm4(bh[j][0], bh[j][1], bh[j][2], bh[j][3], b_addr(j, 2 * ks));
        // pass 0: Ah * Bh
#pragma unroll
        for (int mi = 0; mi < 4; mi++)
#pragma unroll
            for (int ni = 0; ni < 4; ni++) {
                int j = ni >> 1, o = (ni & 1) * 2;
                mma16816(acc[mi][ni][0], acc[mi][ni][1], acc[mi][ni][2], acc[mi][ni][3],
                         af[mi][0], af[mi][1], af[mi][2], af[mi][3], bh[j][o], bh[j][o + 1]);
            }
        // pass 1: Ah * Bl
#pragma unroll
        for (int j = 0; j < 2; j++)
            ldsm4(bl[j][0], bl[j][1], bl[j][2], bl[j][3], b_addr(j, 8 + 2 * ks));
#pragma unroll
        for (int mi = 0; mi < 4; mi++)
#pragma unroll
            for (int ni = 0; ni < 4; ni++) {
                int j = ni >> 1, o = (ni & 1) * 2;
                mma16816(acc[mi][ni][0], acc[mi][ni][1], acc[mi][ni][2], acc[mi][ni][3],
                         af[mi][0], af[mi][1], af[mi][2], af[mi][3], bl[j][o], bl[j][o + 1]);
            }
        // pass 2: Al * Bh  (af <- Al; af dead after pass1)
#pragma unroll
        for (int mi = 0; mi < 4; mi++)
            ldsm4(af[mi][0], af[mi][1], af[mi][2], af[mi][3], a_addr(mi, 8 + 2 * ks));
#pragma unroll
        for (int mi = 0; mi < 4; mi++)
#pragma unroll
            for (int ni = 0; ni < 4; ni++) {
                int j = ni >> 1, o = (ni & 1) * 2;
                mma16816(acc[mi][ni][0], acc[mi][ni][1], acc[mi][ni][2], acc[mi][ni][3],
                         af[mi][0], af[mi][1], af[mi][2], af[mi][3], bh[j][o], bh[j][o + 1]);
            }
    }

    // ---- epilogue: stores + fused per-row argmax partials ----
#pragma unroll
    for (int mi = 0; mi < 4; mi++) {
        int lr = wr + mi * 16 + (lane >> 2);
        float* p0 = C + (size_t)(m0 + lr) * SIMCOLS + n0 + wc + (lane & 3) * 2;
        float* p1 = p0 + (size_t)8 * SIMCOLS;
        ull k0 = 0, k1 = 0;
        int yv0 = -1, yv1 = -1;
        if (domax) { yv0 = ys[lr]; yv1 = ys[lr + 8]; }
#pragma unroll
        for (int ni = 0; ni < 4; ni++) {
            float c0 = acc[mi][ni][0], c1 = acc[mi][ni][1];
            float c2 = acc[mi][ni][2], c3 = acc[mi][ni][3];
            *(float2*)(p0 + ni * 8) = make_float2(c0, c1);
            *(float2*)(p1 + ni * 8) = make_float2(c2, c3);
            if (domax) {
                int col = n0 + wc + ni * 8 + (lane & 3) * 2;
                float v0 = c0 + (col     == yv0 ? 2.0f : 0.0f);
                float v1 = c1 + (col + 1 == yv0 ? 2.0f : 0.0f);
                float v2 = c2 + (col     == yv1 ? 2.0f : 0.0f);
                float v3 = c3 + (col + 1 == yv1 ? 2.0f : 0.0f);
                ull q;
                q = ((ull)fkey(v0) << 32) | (u32)(0xFFFFFFFFu - (u32)col);       if (q > k0) k0 = q;
                q = ((ull)fkey(v1) << 32) | (u32)(0xFFFFFFFFu - (u32)(col + 1)); if (q > k0) k0 = q;
                q = ((ull)fkey(v2) << 32) | (u32)(0xFFFFFFFFu - (u32)col);       if (q > k1) k1 = q;
                q = ((ull)fkey(v3) << 32) | (u32)(0xFFFFFFFFu - (u32)(col + 1)); if (q > k1) k1 = q;
            }
        }
        if (domax) {
#pragma unroll
            for (int o2 = 1; o2 <= 2; o2 <<= 1) {
                ull t0 = __shfl_xor_sync(0xffffffffu, k0, o2); if (t0 > k0) k0 = t0;
                ull t1 = __shfl_xor_sync(0xffffffffu, k1, o2); if (t1 > k1) k1 = t1;
            }
            if ((lane & 3) == 0) {
                atomicMax(&g_amax[m0 + lr], k0);
                atomicMax(&g_amax[m0 + lr + 8], k1);
            }
        }
    }
}

// ---------------- finalize argmax + segment sums (fused) ----------------
__global__ void segsum_kernel(const float* __restrict__ x, float* __restrict__ out_y) {
    int i = blockIdx.x;          // source row
    int t = threadIdx.x;         // 0..63
    ull k = g_amax[i];
    int idx = (int)(0xFFFFFFFFu - (u32)(k & 0xFFFFFFFFull));
    if (t == 0) { out_y[i] = (float)idx; atomicAdd(&g_counts[idx], 1.0f); }
    atomicAdd(&g_get[idx * DIM + t], x[(size_t)i * DIM + t]);
}

// ---------------- memory update + normalize + slot writes ----------------
__global__ void update_kernel(const float* __restrict__ x, const float* __restrict__ memory,
                              const float* __restrict__ params, float* __restrict__ outm) {
    int r = blockIdx.x;
    int t = threadIdx.x;
    if (r < NPOS) {
        float mom   = params[3];
        float cnt   = g_counts[r];
        float valid = (cnt > 0.1f ? 1.0f : 0.0f) * g_vis[r];
        float msc   = valid * mom + 1.0f - valid;
        float gsc   = (1.0f - mom) * valid;
        float denom = cnt + 1e-8f;
        float v0 = memory[(size_t)r * DIM + t]      * msc + (g_get[r * DIM + t]      / denom) * gsc;
        float v1 = memory[(size_t)r * DIM + t + 32] * msc + (g_get[r * DIM + t + 32] / denom) * gsc;
        float ss = v0 * v0 + v1 * v1;
#pragma unroll
        for (int o = 16; o; o >>= 1) ss += __shfl_xor_sync(0xffffffffu, ss, o);
        float inv = 1.0f / fmaxf(sqrtf(ss), 1e-12f);
        outm[(size_t)r * DIM + t]      = v0 * inv;
        outm[(size_t)r * DIM + t + 32] = v1 * inv;
    } else if (r >= NPOS + LRUC * NNEG && r < NPOS + LRUC * NNEG + NNEG) {
        int xs = NPOS + (r - (NPOS + LRUC * NNEG));
        outm[(size_t)r * DIM + t]      = x[(size_t)xs * DIM + t];
        outm[(size_t)r * DIM + t + 32] = x[(size_t)xs * DIM + t + 32];
    } else {
        outm[(size_t)r * DIM + t]      = memory[(size_t)r * DIM + t];
        outm[(size_t)r * DIM + t + 32] = memory[(size_t)r * DIM + t + 32];
    }
}

// ---------------- launch ----------------
extern "C" void kernel_launch(void* const* d_in, const int* in_sizes, int n_in,
                              void* d_out, int out_size) {
    const float* x = nullptr;
    const int*   y = nullptr;
    const int*   visible = nullptr;
    const float* memory = nullptr;
    const float* params = nullptr;
    for (int i = 0; i < n_in; i++) {
        switch (in_sizes[i]) {
            case XROWS * DIM: x = (const float*)d_in[i]; break;
            case NPOS:        y = (const int*)d_in[i]; break;
            case NPOS / 2:    visible = (const int*)d_in[i]; break;
            case MROWS * DIM: memory = (const float*)d_in[i]; break;
            case 4:           params = (const float*)d_in[i]; break;
            default: break;
        }
    }

    float* sim     = (float*)d_out;
    float* out_y   = sim + (size_t)NPOS * SIMCOLS;
    float* out_mem = out_y + NPOS;

    const int SMEM_TOTAL = 49152 + 512;   // A(32K) + B(16K) + ys
    cudaFuncSetAttribute(gemm_mma, cudaFuncAttributeMaxDynamicSharedMemorySize, SMEM_TOTAL);

    split_kernel<<<2048, 256>>>(x, memory);
    vis_kernel<<<(NPOS / 2 + 255) / 256, 256>>>(visible);
    gemm_mma<<<dim3(SIMCOLS / BN, NPOS / BM), THREADS, SMEM_TOTAL>>>(y, sim);
    segsum_kernel<<<NPOS, 64>>>(x, out_y);
    update_kernel<<<MROWS, 32>>>(x, memory, params, out_mem);
}

// round 14
// speedup vs baseline: 1.2042x; 1.0073x over previous
#include <cuda_runtime.h>
#include <cuda_bf16.h>
#include <cstdint>
#include <cstddef>

#define NPOS 8192
#define NNEG 4096
#define DIM 64
#define MROWS 24576          // NPOS + 4*NNEG
#define XROWS 12288
#define SIMCOLS 24576
#define LRUC 1

#define BM 128
#define BN 64
#define THREADS 128

typedef unsigned long long ull;
typedef uint32_t u32;

// ---------------- device scratch (no allocs allowed) ----------------
__device__ __align__(256) __nv_bfloat16 g_Abf[NPOS * 128];    // [row][Ah(64) | Al(64)]
__device__ __align__(256) __nv_bfloat16 g_Bbf[MROWS * 128];   // [row][Bh(64) | Bl(64)]
__device__ float g_get[NPOS * DIM];
__device__ float g_counts[NPOS];
__device__ float g_vis[NPOS];
__device__ ull   g_amax[NPOS];

// ---------------- PTX helpers ----------------
__device__ __forceinline__ u32 smem_u32(const void* p) {
    u32 a; asm("{ .reg .u64 t; cvta.to.shared.u64 t, %1; cvt.u32.u64 %0, t; }" : "=r"(a) : "l"(p));
    return a;
}
__device__ __forceinline__ void cpasync16(u32 dst, const void* src) {
    asm volatile("cp.async.cg.shared.global [%0], [%1], 16;" :: "r"(dst), "l"(src) : "memory");
}
#define CP_COMMIT()  asm volatile("cp.async.commit_group;" ::: "memory")
#define CP_WAIT(n)   asm volatile("cp.async.wait_group %0;" :: "n"(n) : "memory")

__device__ __forceinline__ void ldsm4(u32& r0, u32& r1, u32& r2, u32& r3, u32 addr) {
    asm volatile("ldmatrix.sync.aligned.m8n8.x4.shared.b16 {%0,%1,%2,%3}, [%4];"
                 : "=r"(r0), "=r"(r1), "=r"(r2), "=r"(r3) : "r"(addr));
}
__device__ __forceinline__ void mma16816(float& d0, float& d1, float& d2, float& d3,
                                         u32 a0, u32 a1, u32 a2, u32 a3, u32 b0, u32 b1) {
    asm volatile("mma.sync.aligned.m16n8k16.row.col.f32.bf16.bf16.f32 "
                 "{%0,%1,%2,%3}, {%4,%5,%6,%7}, {%8,%9}, {%0,%1,%2,%3};"
                 : "+f"(d0), "+f"(d1), "+f"(d2), "+f"(d3)
                 : "r"(a0), "r"(a1), "r"(a2), "r"(a3), "r"(b0), "r"(b1));
}
__device__ __forceinline__ u32 fkey(float v) {
    u32 u = __float_as_uint(v);
    return (u & 0x80000000u) ? ~u : (u | 0x80000000u);
}

// ---------------- split + zero scratch (fused) ----------------
__global__ void split_kernel(const float* __restrict__ x, const float* __restrict__ mem) {
    const int nA = NPOS * DIM, nTot = nA + MROWS * DIM;
    const int gs = gridDim.x * blockDim.x;
    const int t0 = blockIdx.x * blockDim.x + threadIdx.x;
    for (int i = t0; i < nTot; i += gs) {
        float v; __nv_bfloat16* base; int k;
        if (i < nA) { v = x[i];        base = g_Abf + (size_t)(i >> 6) * 128;        k = i & 63; }
        else { int j = i - nA; v = mem[j]; base = g_Bbf + (size_t)(j >> 6) * 128;    k = j & 63; }
        __nv_bfloat16 h = __float2bfloat16_rn(v);
        float r = v - __bfloat162float(h);
        base[k]      = h;
        base[64 + k] = __float2bfloat16_rn(r);
    }
    for (int j = t0; j < NPOS * DIM; j += gs) g_get[j] = 0.0f;
    for (int j = t0; j < NPOS; j += gs) { g_counts[j] = 0.0f; g_vis[j] = 0.0f; g_amax[j] = 0ull; }
}

__global__ void vis_kernel(const int* __restrict__ visible) {
    int i = blockIdx.x * blockDim.x + threadIdx.x;
    if (i < NPOS / 2) g_vis[visible[i]] = 1.0f;
}

// ---------------- bf16 split-GEMM via mma.sync + fused argmax partials ----------------
// C = A*B^T with A=Ah+Al, B=Bh+Bl; sim = AhBh + AhBl + AlBh.
// CTA tile 128x64, 128 threads (4 warps, 2x2 grid, warp tile 64x32), 4 CTAs/SM.
// Per-warp software pipelining: bl prefetch inside pass0; pass2 A-reloads
// staggered per-mi so an LDSM is always in flight ahead of its MMA group.
__global__ void __launch_bounds__(THREADS, 4)
gemm_mma(const int* __restrict__ y, float* __restrict__ C) {
    extern __shared__ char smem[];
    const u32 sb = smem_u32(smem);
    const u32 As = sb;             // 128 rows * 256B = 32KB
    const u32 Bs = sb + 32768;     // 64 rows * 256B = 16KB
    int* ys = (int*)(smem + 49152);

    const int tid  = threadIdx.x;
    const int lane = tid & 31;
    const int w    = tid >> 5;
    const int wm   = w >> 1, wn = w & 1;       // 2x2 warp grid
    const int wr = wm * 64, wc = wn * 32;
    const int m0   = blockIdx.y * BM;
    const int n0   = blockIdx.x * BN;
    const bool domax = (n0 < NPOS);

    // ---- cp.async loads: A 2048 chunks (16 iters), B 1024 chunks (8 iters) ----
#pragma unroll
    for (int h = 0; h < 2; h++)
#pragma unroll
        for (int i = 0; i < 8; i++) {
            int idx = tid + i * THREADS;           // 0..1023 per h
            int r = idx >> 3, c = idx & 7;         // r: 0..127
            u32 dst = As + r * 256 + (u32)(((h * 8) | ((c ^ r) & 7)) * 16);
            cpasync16(dst, g_Abf + (size_t)(m0 + r) * 128 + h * 64 + c * 8);
        }
#pragma unroll
    for (int h = 0; h < 2; h++)
#pragma unroll
        for (int i = 0; i < 4; i++) {
            int idx = tid + i * THREADS;           // 0..511 per h
            int r = idx >> 3, c = idx & 7;         // r: 0..63
            u32 dst = Bs + r * 256 + (u32)(((h * 8) | ((c ^ r) & 7)) * 16);
            cpasync16(dst, g_Bbf + (size_t)(n0 + r) * 128 + h * 64 + c * 8);
        }
    CP_COMMIT();
    if (domax) ys[tid] = y[m0 + tid];

    float acc[4][4][4];
#pragma unroll
    for (int mi = 0; mi < 4; mi++)
#pragma unroll
        for (int ni = 0; ni < 4; ni++)
#pragma unroll
            for (int q = 0; q < 4; q++) acc[mi][ni][q] = 0.0f;

    auto a_addr = [&](int mi, int ch) -> u32 {
        int row = wr + mi * 16 + (lane & 15);
        int cc  = ch + (lane >> 4);
        return As + row * 256 + (u32)(((cc & 8) | ((cc ^ row) & 7)) * 16);
    };
    auto b_addr = [&](int j, int ch) -> u32 {
        int n  = wc + j * 16 + (lane & 7) + ((lane >> 4) << 3);
        int cc = ch + ((lane >> 3) & 1);
        return Bs + n * 256 + (u32)(((cc & 8) | ((cc ^ n) & 7)) * 16);
    };

    CP_WAIT(0);
    __syncthreads();

#pragma unroll
    for (int ks = 0; ks < 4; ks++) {
        u32 af[4][4];   // Ah, later Al
        u32 bh[2][4];   // Bh (held through pass2)
        u32 bl[2][4];   // Bl
#pragma unroll
        for (int mi = 0; mi < 4; mi++)
            ldsm4(af[mi][0], af[mi][1], af[mi][2], af[mi][3], a_addr(mi, 2 * ks));
#pragma unroll
        for (int j = 0; j < 2; j++)
            ldsm4(bh[j][0], bh[j][1], bh[j][2], bh[j][3], b_addr(j, 2 * ks));
        // pass 0: Ah * Bh  (bl prefetch after first mi group)
#pragma unroll
        for (int mi = 0; mi < 4; mi++) {
#pragma unroll
            for (int ni = 0; ni < 4; ni++) {
                int j = ni >> 1, o = (ni & 1) * 2;
                mma16816(acc[mi][ni][0], acc[mi][ni][1], acc[mi][ni][2], acc[mi][ni][3],
                         af[mi][0], af[mi][1], af[mi][2], af[mi][3], bh[j][o], bh[j][o + 1]);
            }
            if (mi == 0) {
#pragma unroll
                for (int j = 0; j < 2; j++)
                    ldsm4(bl[j][0], bl[j][1], bl[j][2], bl[j][3], b_addr(j, 8 + 2 * ks));
            }
        }
        // pass 1: Ah * Bl
#pragma unroll
        for (int mi = 0; mi < 4; mi++)
#pragma unroll
            for (int ni = 0; ni < 4; ni++) {
                int j = ni >> 1, o = (ni & 1) * 2;
                mma16816(acc[mi][ni][0], acc[mi][ni][1], acc[mi][ni][2], acc[mi][ni][3],
                         af[mi][0], af[mi][1], af[mi][2], af[mi][3], bl[j][o], bl[j][o + 1]);
            }
        // pass 2: Al * Bh — staggered reload: af[mi+1] load issues before MMA(mi)
        ldsm4(af[0][0], af[0][1], af[0][2], af[0][3], a_addr(0, 8 + 2 * ks));
#pragma unroll
        for (int mi = 0; mi < 4; mi++) {
            if (mi < 3)
                ldsm4(af[mi + 1][0], af[mi + 1][1], af[mi + 1][2], af[mi + 1][3],
                      a_addr(mi + 1, 8 + 2 * ks));
#pragma unroll
            for (int ni = 0; ni < 4; ni++) {
                int j = ni >> 1, o = (ni & 1) * 2;
                mma16816(acc[mi][ni][0], acc[mi][ni][1], acc[mi][ni][2], acc[mi][ni][3],
                         af[mi][0], af[mi][1], af[mi][2], af[mi][3], bh[j][o], bh[j][o + 1]);
            }
        }
    }

    // ---- epilogue: stores + fused per-row argmax partials ----
#pragma unroll
    for (int mi = 0; mi < 4; mi++) {
        int lr = wr + mi * 16 + (lane >> 2);
        float* p0 = C + (size_t)(m0 + lr) * SIMCOLS + n0 + wc + (lane & 3) * 2;
        float* p1 = p0 + (size_t)8 * SIMCOLS;
        ull k0 = 0, k1 = 0;
        int yv0 = -1, yv1 = -1;
        if (domax) { yv0 = ys[lr]; yv1 = ys[lr + 8]; }
#pragma unroll
        for (int ni = 0; ni < 4; ni++) {
            float c0 = acc[mi][ni][0], c1 = acc[mi][ni][1];
            float c2 = acc[mi][ni][2], c3 = acc[mi][ni][3];
            *(float2*)(p0 + ni * 8) = make_float2(c0, c1);
            *(float2*)(p1 + ni * 8) = make_float2(c2, c3);
            if (domax) {
                int col = n0 + wc + ni * 8 + (lane & 3) * 2;
                float v0 = c0 + (col     == yv0 ? 2.0f : 0.0f);
                float v1 = c1 + (col + 1 == yv0 ? 2.0f : 0.0f);
                float v2 = c2 + (col     == yv1 ? 2.0f : 0.0f);
                float v3 = c3 + (col + 1 == yv1 ? 2.0f : 0.0f);
                ull q;
                q = ((ull)fkey(v0) << 32) | (u32)(0xFFFFFFFFu - (u32)col);       if (q > k0) k0 = q;
                q = ((ull)fkey(v1) << 32) | (u32)(0xFFFFFFFFu - (u32)(col + 1)); if (q > k0) k0 = q;
                q = ((ull)fkey(v2) << 32) | (u32)(0xFFFFFFFFu - (u32)col);       if (q > k1) k1 = q;
                q = ((ull)fkey(v3) << 32) | (u32)(0xFFFFFFFFu - (u32)(col + 1)); if (q > k1) k1 = q;
            }
        }
        if (domax) {
#pragma unroll
            for (int o2 = 1; o2 <= 2; o2 <<= 1) {
                ull t0 = __shfl_xor_sync(0xffffffffu, k0, o2); if (t0 > k0) k0 = t0;
                ull t1 = __shfl_xor_sync(0xffffffffu, k1, o2); if (t1 > k1) k1 = t1;
            }
            if ((lane & 3) == 0) {
                atomicMax(&g_amax[m0 + lr], k0);
                atomicMax(&g_amax[m0 + lr + 8], k1);
            }
        }
    }
}

// ---------------- finalize argmax + segment sums (fused; 4 rows/block) ----------------
__global__ void segsum_kernel(const float* __restrict__ x, float* __restrict__ out_y) {
    int i = blockIdx.x * 4 + (threadIdx.x >> 6);   // source row
    int t = threadIdx.x & 63;
    ull k = g_amax[i];
    int idx = (int)(0xFFFFFFFFu - (u32)(k & 0xFFFFFFFFull));
    if (t == 0) { out_y[i] = (float)idx; atomicAdd(&g_counts[idx], 1.0f); }
    atomicAdd(&g_get[idx * DIM + t], x[(size_t)i * DIM + t]);
}

// ---------------- memory update + normalize + slot writes ----------------
__global__ void update_kernel(const float* __restrict__ x, const float* __restrict__ memory,
                              const float* __restrict__ params, float* __restrict__ outm) {
    int r = blockIdx.x;
    int t = threadIdx.x;
    if (r < NPOS) {
        float mom   = params[3];
        float cnt   = g_counts[r];
        float valid = (cnt > 0.1f ? 1.0f : 0.0f) * g_vis[r];
        float msc   = valid * mom + 1.0f - valid;
        float gsc   = (1.0f - mom) * valid;
        float denom = cnt + 1e-8f;
        float v0 = memory[(size_t)r * DIM + t]      * msc + (g_get[r * DIM + t]      / denom) * gsc;
        float v1 = memory[(size_t)r * DIM + t + 32] * msc + (g_get[r * DIM + t + 32] / denom) * gsc;
        float ss = v0 * v0 + v1 * v1;
#pragma unroll
        for (int o = 16; o; o >>= 1) ss += __shfl_xor_sync(0xffffffffu, ss, o);
        float inv = 1.0f / fmaxf(sqrtf(ss), 1e-12f);
        outm[(size_t)r * DIM + t]      = v0 * inv;
        outm[(size_t)r * DIM + t + 32] = v1 * inv;
    } else if (r >= NPOS + LRUC * NNEG && r < NPOS + LRUC * NNEG + NNEG) {
        int xs = NPOS + (r - (NPOS + LRUC * NNEG));
        outm[(size_t)r * DIM + t]      = x[(size_t)xs * DIM + t];
        outm[(size_t)r * DIM + t + 32] = x[(size_t)xs * DIM + t + 32];
    } else {
        outm[(size_t)r * DIM + t]      = memory[(size_t)r * DIM + t];
        outm[(size_t)r * DIM + t + 32] = memory[(size_t)r * DIM + t + 32];
    }
}

// ---------------- launch ----------------
extern "C" void kernel_launch(void* const* d_in, const int* in_sizes, int n_in,
                              void* d_out, int out_size) {
    const float* x = nullptr;
    const int*   y = nullptr;
    const int*   visible = nullptr;
    const float* memory = nullptr;
    const float* params = nullptr;
    for (int i = 0; i < n_in; i++) {
        switch (in_sizes[i]) {
            case XROWS * DIM: x = (const float*)d_in[i]; break;
            case NPOS:        y = (const int*)d_in[i]; break;
            case NPOS / 2:    visible = (const int*)d_in[i]; break;
            case MROWS * DIM: memory = (const float*)d_in[i]; break;
            case 4:           params = (const float*)d_in[i]; break;
            default: break;
        }
    }

    float* sim     = (float*)d_out;
    float* out_y   = sim + (size_t)NPOS * SIMCOLS;
    float* out_mem = out_y + NPOS;

    const int SMEM_TOTAL = 49152 + 512;   // A(32K) + B(16K) + ys
    cudaFuncSetAttribute(gemm_mma, cudaFuncAttributeMaxDynamicSharedMemorySize, SMEM_TOTAL);

    split_kernel<<<2048, 256>>>(x, memory);
    vis_kernel<<<(NPOS / 2 + 255) / 256, 256>>>(visible);
    gemm_mma<<<dim3(SIMCOLS / BN, NPOS / BM), THREADS, SMEM_TOTAL>>>(y, sim);
    segsum_kernel<<<NPOS / 4, 256>>>(x, out_y);
    update_kernel<<<MROWS, 32>>>(x, memory, params, out_mem);
}

// round 15
// speedup vs baseline: 1.2743x; 1.0582x over previous
#include <cuda_runtime.h>
#include <cuda_bf16.h>
#include <cstdint>
#include <cstddef>

#define NPOS 8192
#define NNEG 4096
#define DIM 64
#define MROWS 24576          // NPOS + 4*NNEG
#define XROWS 12288
#define SIMCOLS 24576
#define LRUC 1

#define BM 128
#define BN 64
#define THREADS 128

typedef unsigned long long ull;
typedef uint32_t u32;

// ---------------- device scratch (no allocs allowed) ----------------
__device__ __align__(256) __nv_bfloat16 g_Abf[NPOS * 128];    // [row][Ah(64) | Al(64)]
__device__ __align__(256) __nv_bfloat16 g_Bbf[MROWS * 128];   // [row][Bh(64) | Bl(64)]
__device__ float g_get[NPOS * DIM];
__device__ float g_counts[NPOS];
__device__ float g_vis[NPOS];
__device__ ull   g_amax[NPOS];

// ---------------- PTX helpers ----------------
__device__ __forceinline__ u32 smem_u32(const void* p) {
    u32 a; asm("{ .reg .u64 t; cvta.to.shared.u64 t, %1; cvt.u32.u64 %0, t; }" : "=r"(a) : "l"(p));
    return a;
}
__device__ __forceinline__ void cpasync16(u32 dst, const void* src) {
    asm volatile("cp.async.cg.shared.global [%0], [%1], 16;" :: "r"(dst), "l"(src) : "memory");
}
#define CP_COMMIT()  asm volatile("cp.async.commit_group;" ::: "memory")
#define CP_WAIT(n)   asm volatile("cp.async.wait_group %0;" :: "n"(n) : "memory")

__device__ __forceinline__ void ldsm4(u32& r0, u32& r1, u32& r2, u32& r3, u32 addr) {
    asm volatile("ldmatrix.sync.aligned.m8n8.x4.shared.b16 {%0,%1,%2,%3}, [%4];"
                 : "=r"(r0), "=r"(r1), "=r"(r2), "=r"(r3) : "r"(addr));
}
__device__ __forceinline__ void mma16816(float& d0, float& d1, float& d2, float& d3,
                                         u32 a0, u32 a1, u32 a2, u32 a3, u32 b0, u32 b1) {
    asm volatile("mma.sync.aligned.m16n8k16.row.col.f32.bf16.bf16.f32 "
                 "{%0,%1,%2,%3}, {%4,%5,%6,%7}, {%8,%9}, {%0,%1,%2,%3};"
                 : "+f"(d0), "+f"(d1), "+f"(d2), "+f"(d3)
                 : "r"(a0), "r"(a1), "r"(a2), "r"(a3), "r"(b0), "r"(b1));
}
__device__ __forceinline__ u32 fkey(float v) {
    u32 u = __float_as_uint(v);
    return (u & 0x80000000u) ? ~u : (u | 0x80000000u);
}

// ---------------- split + zero scratch (fused, float2-vectorized) ----------------
__global__ void split_kernel(const float* __restrict__ x, const float* __restrict__ mem) {
    const int nA = NPOS * DIM;
    const int nTot2 = (nA + MROWS * DIM) / 2;       // element PAIRS
    const int gs = gridDim.x * blockDim.x;
    const int t0 = blockIdx.x * blockDim.x + threadIdx.x;
    for (int i = t0; i < nTot2; i += gs) {
        int e = i * 2;
        float2 v; __nv_bfloat16* base; int k;
        if (e < nA) { v = *(const float2*)(x + e);        base = g_Abf + (size_t)(e >> 6) * 128; k = e & 63; }
        else { int j = e - nA; v = *(const float2*)(mem + j); base = g_Bbf + (size_t)(j >> 6) * 128; k = j & 63; }
        __nv_bfloat16 h0 = __float2bfloat16_rn(v.x);
        __nv_bfloat16 h1 = __float2bfloat16_rn(v.y);
        float r0 = v.x - __bfloat162float(h0);
        float r1 = v.y - __bfloat162float(h1);
        __nv_bfloat162 hh; hh.x = h0; hh.y = h1;
        __nv_bfloat162 ll; ll.x = __float2bfloat16_rn(r0); ll.y = __float2bfloat16_rn(r1);
        *(__nv_bfloat162*)(base + k)      = hh;
        *(__nv_bfloat162*)(base + 64 + k) = ll;
    }
    for (int j = t0; j < NPOS * DIM; j += gs) g_get[j] = 0.0f;
    for (int j = t0; j < NPOS; j += gs) { g_counts[j] = 0.0f; g_vis[j] = 0.0f; g_amax[j] = 0ull; }
}

// ---------------- bf16 split-GEMM via mma.sync + fused argmax partials ----------------
// C = A*B^T with A=Ah+Al, B=Bh+Bl; sim = AhBh + AhBl + AlBh.
// CTA tile 128x64, 128 threads (4 warps, 2x2 grid, warp tile 64x32), 4 CTAs/SM.
__global__ void __launch_bounds__(THREADS, 4)
gemm_mma(const int* __restrict__ y, float* __restrict__ C) {
    extern __shared__ char smem[];
    const u32 sb = smem_u32(smem);
    const u32 As = sb;             // 128 rows * 256B = 32KB
    const u32 Bs = sb + 32768;     // 64 rows * 256B = 16KB
    int* ys = (int*)(smem + 49152);

    const int tid  = threadIdx.x;
    const int lane = tid & 31;
    const int w    = tid >> 5;
    const int wm   = w >> 1, wn = w & 1;       // 2x2 warp grid
    const int wr = wm * 64, wc = wn * 32;
    const int m0   = blockIdx.y * BM;
    const int n0   = blockIdx.x * BN;
    const bool domax = (n0 < NPOS);

    // ---- cp.async loads: A 2048 chunks (16 iters), B 1024 chunks (8 iters) ----
#pragma unroll
    for (int h = 0; h < 2; h++)
#pragma unroll
        for (int i = 0; i < 8; i++) {
            int idx = tid + i * THREADS;           // 0..1023 per h
            int r = idx >> 3, c = idx & 7;         // r: 0..127
            u32 dst = As + r * 256 + (u32)(((h * 8) | ((c ^ r) & 7)) * 16);
            cpasync16(dst, g_Abf + (size_t)(m0 + r) * 128 + h * 64 + c * 8);
        }
#pragma unroll
    for (int h = 0; h < 2; h++)
#pragma unroll
        for (int i = 0; i < 4; i++) {
            int idx = tid + i * THREADS;           // 0..511 per h
            int r = idx >> 3, c = idx & 7;         // r: 0..63
            u32 dst = Bs + r * 256 + (u32)(((h * 8) | ((c ^ r) & 7)) * 16);
            cpasync16(dst, g_Bbf + (size_t)(n0 + r) * 128 + h * 64 + c * 8);
        }
    CP_COMMIT();
    if (domax) ys[tid] = y[m0 + tid];

    float acc[4][4][4];
#pragma unroll
    for (int mi = 0; mi < 4; mi++)
#pragma unroll
        for (int ni = 0; ni < 4; ni++)
#pragma unroll
            for (int q = 0; q < 4; q++) acc[mi][ni][q] = 0.0f;

    auto a_addr = [&](int mi, int ch) -> u32 {
        int row = wr + mi * 16 + (lane & 15);
        int cc  = ch + (lane >> 4);
        return As + row * 256 + (u32)(((cc & 8) | ((cc ^ row) & 7)) * 16);
    };
    auto b_addr = [&](int j, int ch) -> u32 {
        int n  = wc + j * 16 + (lane & 7) + ((lane >> 4) << 3);
        int cc = ch + ((lane >> 3) & 1);
        return Bs + n * 256 + (u32)(((cc & 8) | ((cc ^ n) & 7)) * 16);
    };

    CP_WAIT(0);
    __syncthreads();

#pragma unroll
    for (int ks = 0; ks < 4; ks++) {
        u32 af[4][4];   // Ah, later Al
        u32 bh[2][4];   // Bh (held through pass2)
        u32 bl[2][4];   // Bl
#pragma unroll
        for (int mi = 0; mi < 4; mi++)
            ldsm4(af[mi][0], af[mi][1], af[mi][2], af[mi][3], a_addr(mi, 2 * ks));
#pragma unroll
        for (int j = 0; j < 2; j++)
            ldsm4(bh[j][0], bh[j][1], bh[j][2], bh[j][3], b_addr(j, 2 * ks));
        // pass 0: Ah * Bh  (bl prefetch after first mi group)
#pragma unroll
        for (int mi = 0; mi < 4; mi++) {
#pragma unroll
            for (int ni = 0; ni < 4; ni++) {
                int j = ni >> 1, o = (ni & 1) * 2;
                mma16816(acc[mi][ni][0], acc[mi][ni][1], acc[mi][ni][2], acc[mi][ni][3],
                         af[mi][0], af[mi][1], af[mi][2], af[mi][3], bh[j][o], bh[j][o + 1]);
            }
            if (mi == 0) {
#pragma unroll
                for (int j = 0; j < 2; j++)
                    ldsm4(bl[j][0], bl[j][1], bl[j][2], bl[j][3], b_addr(j, 8 + 2 * ks));
            }
        }
        // pass 1: Ah * Bl
#pragma unroll
        for (int mi = 0; mi < 4; mi++)
#pragma unroll
            for (int ni = 0; ni < 4; ni++) {
                int j = ni >> 1, o = (ni & 1) * 2;
                mma16816(acc[mi][ni][0], acc[mi][ni][1], acc[mi][ni][2], acc[mi][ni][3],
                         af[mi][0], af[mi][1], af[mi][2], af[mi][3], bl[j][o], bl[j][o + 1]);
            }
        // pass 2: Al * Bh — staggered reload: af[mi+1] load issues before MMA(mi)
        ldsm4(af[0][0], af[0][1], af[0][2], af[0][3], a_addr(0, 8 + 2 * ks));
#pragma unroll
        for (int mi = 0; mi < 4; mi++) {
            if (mi < 3)
                ldsm4(af[mi + 1][0], af[mi + 1][1], af[mi + 1][2], af[mi + 1][3],
                      a_addr(mi + 1, 8 + 2 * ks));
#pragma unroll
            for (int ni = 0; ni < 4; ni++) {
                int j = ni >> 1, o = (ni & 1) * 2;
                mma16816(acc[mi][ni][0], acc[mi][ni][1], acc[mi][ni][2], acc[mi][ni][3],
                         af[mi][0], af[mi][1], af[mi][2], af[mi][3], bh[j][o], bh[j][o + 1]);
            }
        }
    }

    // ---- epilogue: stores + fused per-row argmax partials ----
#pragma unroll
    for (int mi = 0; mi < 4; mi++) {
        int lr = wr + mi * 16 + (lane >> 2);
        float* p0 = C + (size_t)(m0 + lr) * SIMCOLS + n0 + wc + (lane & 3) * 2;
        float* p1 = p0 + (size_t)8 * SIMCOLS;
        ull k0 = 0, k1 = 0;
        int yv0 = -1, yv1 = -1;
        if (domax) { yv0 = ys[lr]; yv1 = ys[lr + 8]; }
#pragma unroll
        for (int ni = 0; ni < 4; ni++) {
            float c0 = acc[mi][ni][0], c1 = acc[mi][ni][1];
            float c2 = acc[mi][ni][2], c3 = acc[mi][ni][3];
            *(float2*)(p0 + ni * 8) = make_float2(c0, c1);
            *(float2*)(p1 + ni * 8) = make_float2(c2, c3);
            if (domax) {
                int col = n0 + wc + ni * 8 + (lane & 3) * 2;
                float v0 = c0 + (col     == yv0 ? 2.0f : 0.0f);
                float v1 = c1 + (col + 1 == yv0 ? 2.0f : 0.0f);
                float v2 = c2 + (col     == yv1 ? 2.0f : 0.0f);
                float v3 = c3 + (col + 1 == yv1 ? 2.0f : 0.0f);
                ull q;
                q = ((ull)fkey(v0) << 32) | (u32)(0xFFFFFFFFu - (u32)col);       if (q > k0) k0 = q;
                q = ((ull)fkey(v1) << 32) | (u32)(0xFFFFFFFFu - (u32)(col + 1)); if (q > k0) k0 = q;
                q = ((ull)fkey(v2) << 32) | (u32)(0xFFFFFFFFu - (u32)col);       if (q > k1) k1 = q;
                q = ((ull)fkey(v3) << 32) | (u32)(0xFFFFFFFFu - (u32)(col + 1)); if (q > k1) k1 = q;
            }
        }
        if (domax) {
#pragma unroll
            for (int o2 = 1; o2 <= 2; o2 <<= 1) {
                ull t0 = __shfl_xor_sync(0xffffffffu, k0, o2); if (t0 > k0) k0 = t0;
                ull t1 = __shfl_xor_sync(0xffffffffu, k1, o2); if (t1 > k1) k1 = t1;
            }
            if ((lane & 3) == 0) {
                atomicMax(&g_amax[m0 + lr], k0);
                atomicMax(&g_amax[m0 + lr + 8], k1);
            }
        }
    }
}

// ---- finalize argmax + segment sums + vis scatter (fused; 4 rows/block) ----
__global__ void segsum_kernel(const float* __restrict__ x, const int* __restrict__ visible,
                              float* __restrict__ out_y) {
    int g = blockIdx.x * 256 + threadIdx.x;
    if (g < NPOS / 2) g_vis[visible[g]] = 1.0f;      // vis scatter (g_vis zeroed in split)
    int i = blockIdx.x * 4 + (threadIdx.x >> 6);     // source row
    int t = threadIdx.x & 63;
    ull k = g_amax[i];
    int idx = (int)(0xFFFFFFFFu - (u32)(k & 0xFFFFFFFFull));
    if (t == 0) { out_y[i] = (float)idx; atomicAdd(&g_counts[idx], 1.0f); }
    atomicAdd(&g_get[idx * DIM + t], x[(size_t)i * DIM + t]);
}

// ---------------- memory update + normalize + slot writes (8 rows/block) ----------------
__global__ void update_kernel(const float* __restrict__ x, const float* __restrict__ memory,
                              const float* __restrict__ params, float* __restrict__ outm) {
    int r = blockIdx.x * 8 + (threadIdx.x >> 5);
    int t = threadIdx.x & 31;
    if (r < NPOS) {
        float mom   = params[3];
        float cnt   = g_counts[r];
        float valid = (cnt > 0.1f ? 1.0f : 0.0f) * g_vis[r];
        float msc   = valid * mom + 1.0f - valid;
        float gsc   = (1.0f - mom) * valid;
        float denom = cnt + 1e-8f;
        float v0 = memory[(size_t)r * DIM + t]      * msc + (g_get[r * DIM + t]      / denom) * gsc;
        float v1 = memory[(size_t)r * DIM + t + 32] * msc + (g_get[r * DIM + t + 32] / denom) * gsc;
        float ss = v0 * v0 + v1 * v1;
#pragma unroll
        for (int o = 16; o; o >>= 1) ss += __shfl_xor_sync(0xffffffffu, ss, o);
        float inv = 1.0f / fmaxf(sqrtf(ss), 1e-12f);
        outm[(size_t)r * DIM + t]      = v0 * inv;
        outm[(size_t)r * DIM + t + 32] = v1 * inv;
    } else if (r >= NPOS + LRUC * NNEG && r < NPOS + LRUC * NNEG + NNEG) {
        int xs = NPOS + (r - (NPOS + LRUC * NNEG));
        outm[(size_t)r * DIM + t]      = x[(size_t)xs * DIM + t];
        outm[(size_t)r * DIM + t + 32] = x[(size_t)xs * DIM + t + 32];
    } else {
        outm[(size_t)r * DIM + t]      = memory[(size_t)r * DIM + t];
        outm[(size_t)r * DIM + t + 32] = memory[(size_t)r * DIM + t + 32];
    }
}

// ---------------- launch ----------------
extern "C" void kernel_launch(void* const* d_in, const int* in_sizes, int n_in,
                              void* d_out, int out_size) {
    const float* x = nullptr;
    const int*   y = nullptr;
    const int*   visible = nullptr;
    const float* memory = nullptr;
    const float* params = nullptr;
    for (int i = 0; i < n_in; i++) {
        switch (in_sizes[i]) {
            case XROWS * DIM: x = (const float*)d_in[i]; break;
            case NPOS:        y = (const int*)d_in[i]; break;
            case NPOS / 2:    visible = (const int*)d_in[i]; break;
            case MROWS * DIM: memory = (const float*)d_in[i]; break;
            case 4:           params = (const float*)d_in[i]; break;
            default: break;
        }
    }

    float* sim     = (float*)d_out;
    float* out_y   = sim + (size_t)NPOS * SIMCOLS;
    float* out_mem = out_y + NPOS;

    const int SMEM_TOTAL = 49152 + 512;   // A(32K) + B(16K) + ys
    cudaFuncSetAttribute(gemm_mma, cudaFuncAttributeMaxDynamicSharedMemorySize, SMEM_TOTAL);

    split_kernel<<<2048, 256>>>(x, memory);
    gemm_mma<<<dim3(SIMCOLS / BN, NPOS / BM), THREADS, SMEM_TOTAL>>>(y, sim);
    segsum_kernel<<<NPOS / 4, 256>>>(x, visible, out_y);
    update_kernel<<<MROWS / 8, 256>>>(x, memory, params, out_mem);
}

// round 16
// speedup vs baseline: 1.2798x; 1.0043x over previous
#include <cuda_runtime.h>
#include <cuda_bf16.h>
#include <cstdint>
#include <cstddef>

#define NPOS 8192
#define NNEG 4096
#define DIM 64
#define MROWS 24576          // NPOS + 4*NNEG
#define XROWS 12288
#define SIMCOLS 24576
#define LRUC 1

#define BM 128
#define BN 64
#define THREADS 128

typedef unsigned long long ull;
typedef uint32_t u32;

// ---------------- device scratch (no allocs allowed) ----------------
__device__ __align__(256) __nv_bfloat16 g_Abf[NPOS * 128];    // [row][Ah(64) | Al(64)]
__device__ __align__(256) __nv_bfloat16 g_Bbf[MROWS * 128];   // [row][Bh(64) | Bl(64)]
__device__ float g_get[NPOS * DIM];
__device__ float g_counts[NPOS];
__device__ float g_vis[NPOS];
__device__ ull   g_amax[NPOS];

// ---------------- PTX helpers ----------------
__device__ __forceinline__ u32 smem_u32(const void* p) {
    u32 a; asm("{ .reg .u64 t; cvta.to.shared.u64 t, %1; cvt.u32.u64 %0, t; }" : "=r"(a) : "l"(p));
    return a;
}
__device__ __forceinline__ void cpasync16(u32 dst, const void* src) {
    asm volatile("cp.async.cg.shared.global [%0], [%1], 16;" :: "r"(dst), "l"(src) : "memory");
}
#define CP_COMMIT()  asm volatile("cp.async.commit_group;" ::: "memory")
#define CP_WAIT(n)   asm volatile("cp.async.wait_group %0;" :: "n"(n) : "memory")

__device__ __forceinline__ void ldsm4(u32& r0, u32& r1, u32& r2, u32& r3, u32 addr) {
    asm volatile("ldmatrix.sync.aligned.m8n8.x4.shared.b16 {%0,%1,%2,%3}, [%4];"
                 : "=r"(r0), "=r"(r1), "=r"(r2), "=r"(r3) : "r"(addr));
}
__device__ __forceinline__ void mma16816(float& d0, float& d1, float& d2, float& d3,
                                         u32 a0, u32 a1, u32 a2, u32 a3, u32 b0, u32 b1) {
    asm volatile("mma.sync.aligned.m16n8k16.row.col.f32.bf16.bf16.f32 "
                 "{%0,%1,%2,%3}, {%4,%5,%6,%7}, {%8,%9}, {%0,%1,%2,%3};"
                 : "+f"(d0), "+f"(d1), "+f"(d2), "+f"(d3)
                 : "r"(a0), "r"(a1), "r"(a2), "r"(a3), "r"(b0), "r"(b1));
}
__device__ __forceinline__ u32 fkey(float v) {
    u32 u = __float_as_uint(v);
    return (u & 0x80000000u) ? ~u : (u | 0x80000000u);
}

// ---------------- split + zero scratch (fused, float2-vectorized) ----------------
__global__ void split_kernel(const float* __restrict__ x, const float* __restrict__ mem) {
    const int nA = NPOS * DIM;
    const int nTot2 = (nA + MROWS * DIM) / 2;       // element PAIRS
    const int gs = gridDim.x * blockDim.x;
    const int t0 = blockIdx.x * blockDim.x + threadIdx.x;
    for (int i = t0; i < nTot2; i += gs) {
        int e = i * 2;
        float2 v; __nv_bfloat16* base; int k;
        if (e < nA) { v = *(const float2*)(x + e);        base = g_Abf + (size_t)(e >> 6) * 128; k = e & 63; }
        else { int j = e - nA; v = *(const float2*)(mem + j); base = g_Bbf + (size_t)(j >> 6) * 128; k = j & 63; }
        __nv_bfloat16 h0 = __float2bfloat16_rn(v.x);
        __nv_bfloat16 h1 = __float2bfloat16_rn(v.y);
        float r0 = v.x - __bfloat162float(h0);
        float r1 = v.y - __bfloat162float(h1);
        __nv_bfloat162 hh; hh.x = h0; hh.y = h1;
        __nv_bfloat162 ll; ll.x = __float2bfloat16_rn(r0); ll.y = __float2bfloat16_rn(r1);
        *(__nv_bfloat162*)(base + k)      = hh;
        *(__nv_bfloat162*)(base + 64 + k) = ll;
    }
    for (int j = t0; j < NPOS * DIM; j += gs) g_get[j] = 0.0f;
    for (int j = t0; j < NPOS; j += gs) { g_counts[j] = 0.0f; g_vis[j] = 0.0f; g_amax[j] = 0ull; }
}

// ---------------- bf16 split-GEMM via mma.sync + fused argmax partials ----------------
// C = A*B^T with A=Ah+Al, B=Bh+Bl; sim = AhBh + AhBl + AlBh.
// CTA tile 128x64, 128 threads (4 warps, 2x2 grid, warp tile 64x32), 4 CTAs/SM.
__global__ void __launch_bounds__(THREADS, 4)
gemm_mma(const int* __restrict__ y, float* __restrict__ C) {
    extern __shared__ char smem[];
    const u32 sb = smem_u32(smem);
    const u32 As = sb;             // 128 rows * 256B = 32KB
    const u32 Bs = sb + 32768;     // 64 rows * 256B = 16KB
    int* ys = (int*)(smem + 49152);

    const int tid  = threadIdx.x;
    const int lane = tid & 31;
    const int w    = tid >> 5;
    const int wm   = w >> 1, wn = w & 1;       // 2x2 warp grid
    const int wr = wm * 64, wc = wn * 32;
    const int m0   = blockIdx.y * BM;
    const int n0   = blockIdx.x * BN;
    const bool domax = (n0 < NPOS);

    // ---- cp.async loads: A 2048 chunks (16 iters), B 1024 chunks (8 iters) ----
#pragma unroll
    for (int h = 0; h < 2; h++)
#pragma unroll
        for (int i = 0; i < 8; i++) {
            int idx = tid + i * THREADS;           // 0..1023 per h
            int r = idx >> 3, c = idx & 7;         // r: 0..127
            u32 dst = As + r * 256 + (u32)(((h * 8) | ((c ^ r) & 7)) * 16);
            cpasync16(dst, g_Abf + (size_t)(m0 + r) * 128 + h * 64 + c * 8);
        }
#pragma unroll
    for (int h = 0; h < 2; h++)
#pragma unroll
        for (int i = 0; i < 4; i++) {
            int idx = tid + i * THREADS;           // 0..511 per h
            int r = idx >> 3, c = idx & 7;         // r: 0..63
            u32 dst = Bs + r * 256 + (u32)(((h * 8) | ((c ^ r) & 7)) * 16);
            cpasync16(dst, g_Bbf + (size_t)(n0 + r) * 128 + h * 64 + c * 8);
        }
    CP_COMMIT();
    if (domax) ys[tid] = y[m0 + tid];

    float acc[4][4][4];
#pragma unroll
    for (int mi = 0; mi < 4; mi++)
#pragma unroll
        for (int ni = 0; ni < 4; ni++)
#pragma unroll
            for (int q = 0; q < 4; q++) acc[mi][ni][q] = 0.0f;

    auto a_addr = [&](int mi, int ch) -> u32 {
        int row = wr + mi * 16 + (lane & 15);
        int cc  = ch + (lane >> 4);
        return As + row * 256 + (u32)(((cc & 8) | ((cc ^ row) & 7)) * 16);
    };
    auto b_addr = [&](int j, int ch) -> u32 {
        int n  = wc + j * 16 + (lane & 7) + ((lane >> 4) << 3);
        int cc = ch + ((lane >> 3) & 1);
        return Bs + n * 256 + (u32)(((cc & 8) | ((cc ^ n) & 7)) * 16);
    };

    CP_WAIT(0);
    __syncthreads();

#pragma unroll
    for (int ks = 0; ks < 4; ks++) {
        u32 af[4][4];   // Ah, later Al
        u32 bh[2][4];   // Bh (held through pass2)
        u32 bl[2][4];   // Bl
#pragma unroll
        for (int mi = 0; mi < 4; mi++)
            ldsm4(af[mi][0], af[mi][1], af[mi][2], af[mi][3], a_addr(mi, 2 * ks));
#pragma unroll
        for (int j = 0; j < 2; j++)
            ldsm4(bh[j][0], bh[j][1], bh[j][2], bh[j][3], b_addr(j, 2 * ks));
        // pass 0: Ah * Bh  (bl prefetch after first mi group)
#pragma unroll
        for (int mi = 0; mi < 4; mi++) {
#pragma unroll
            for (int ni = 0; ni < 4; ni++) {
                int j = ni >> 1, o = (ni & 1) * 2;
                mma16816(acc[mi][ni][0], acc[mi][ni][1], acc[mi][ni][2], acc[mi][ni][3],
                         af[mi][0], af[mi][1], af[mi][2], af[mi][3], bh[j][o], bh[j][o + 1]);
            }
            if (mi == 0) {
#pragma unroll
                for (int j = 0; j < 2; j++)
                    ldsm4(bl[j][0], bl[j][1], bl[j][2], bl[j][3], b_addr(j, 8 + 2 * ks));
            }
        }
        // pass 1: Ah * Bl
#pragma unroll
        for (int mi = 0; mi < 4; mi++)
#pragma unroll
            for (int ni = 0; ni < 4; ni++) {
                int j = ni >> 1, o = (ni & 1) * 2;
                mma16816(acc[mi][ni][0], acc[mi][ni][1], acc[mi][ni][2], acc[mi][ni][3],
                         af[mi][0], af[mi][1], af[mi][2], af[mi][3], bl[j][o], bl[j][o + 1]);
            }
        // pass 2: Al * Bh — staggered reload: af[mi+1] load issues before MMA(mi)
        ldsm4(af[0][0], af[0][1], af[0][2], af[0][3], a_addr(0, 8 + 2 * ks));
#pragma unroll
        for (int mi = 0; mi < 4; mi++) {
            if (mi < 3)
                ldsm4(af[mi + 1][0], af[mi + 1][1], af[mi + 1][2], af[mi + 1][3],
                      a_addr(mi + 1, 8 + 2 * ks));
#pragma unroll
            for (int ni = 0; ni < 4; ni++) {
                int j = ni >> 1, o = (ni & 1) * 2;
                mma16816(acc[mi][ni][0], acc[mi][ni][1], acc[mi][ni][2], acc[mi][ni][3],
                         af[mi][0], af[mi][1], af[mi][2], af[mi][3], bh[j][o], bh[j][o + 1]);
            }
        }
    }

    // ---- epilogue: stores + fused per-row argmax partials ----
#pragma unroll
    for (int mi = 0; mi < 4; mi++) {
        int lr = wr + mi * 16 + (lane >> 2);
        float* p0 = C + (size_t)(m0 + lr) * SIMCOLS + n0 + wc + (lane & 3) * 2;
        float* p1 = p0 + (size_t)8 * SIMCOLS;
        ull k0 = 0, k1 = 0;
        int yv0 = -1, yv1 = -1;
        if (domax) { yv0 = ys[lr]; yv1 = ys[lr + 8]; }
#pragma unroll
        for (int ni = 0; ni < 4; ni++) {
            float c0 = acc[mi][ni][0], c1 = acc[mi][ni][1];
            float c2 = acc[mi][ni][2], c3 = acc[mi][ni][3];
            *(float2*)(p0 + ni * 8) = make_float2(c0, c1);
            *(float2*)(p1 + ni * 8) = make_float2(c2, c3);
            if (domax) {
                int col = n0 + wc + ni * 8 + (lane & 3) * 2;
                float v0 = c0 + (col     == yv0 ? 2.0f : 0.0f);
                float v1 = c1 + (col + 1 == yv0 ? 2.0f : 0.0f);
                float v2 = c2 + (col     == yv1 ? 2.0f : 0.0f);
                float v3 = c3 + (col + 1 == yv1 ? 2.0f : 0.0f);
                ull q;
                q = ((ull)fkey(v0) << 32) | (u32)(0xFFFFFFFFu - (u32)col);       if (q > k0) k0 = q;
                q = ((ull)fkey(v1) << 32) | (u32)(0xFFFFFFFFu - (u32)(col + 1)); if (q > k0) k0 = q;
                q = ((ull)fkey(v2) << 32) | (u32)(0xFFFFFFFFu - (u32)col);       if (q > k1) k1 = q;
                q = ((ull)fkey(v3) << 32) | (u32)(0xFFFFFFFFu - (u32)(col + 1)); if (q > k1) k1 = q;
            }
        }
        if (domax) {
#pragma unroll
            for (int o2 = 1; o2 <= 2; o2 <<= 1) {
                ull t0 = __shfl_xor_sync(0xffffffffu, k0, o2); if (t0 > k0) k0 = t0;
                ull t1 = __shfl_xor_sync(0xffffffffu, k1, o2); if (t1 > k1) k1 = t1;
            }
            if ((lane & 3) == 0) {
                atomicMax(&g_amax[m0 + lr], k0);
                atomicMax(&g_amax[m0 + lr + 8], k1);
            }
        }
    }
}

// ---- finalize argmax + segment sums + vis scatter (fused; 4 rows/block) ----
__global__ void segsum_kernel(const float* __restrict__ x, const int* __restrict__ visible,
                              float* __restrict__ out_y) {
    int g = blockIdx.x * 256 + threadIdx.x;
    if (g < NPOS / 2) g_vis[visible[g]] = 1.0f;      // vis scatter (g_vis zeroed in split)
    int i = blockIdx.x * 4 + (threadIdx.x >> 6);     // source row
    int t = threadIdx.x & 63;
    ull k = g_amax[i];
    int idx = (int)(0xFFFFFFFFu - (u32)(k & 0xFFFFFFFFull));
    if (t == 0) { out_y[i] = (float)idx; atomicAdd(&g_counts[idx], 1.0f); }
    atomicAdd(&g_get[idx * DIM + t], x[(size_t)i * DIM + t]);
}

// ---------------- memory update + normalize + slot writes (8 rows/block) ----------------
__global__ void update_kernel(const float* __restrict__ x, const float* __restrict__ memory,
                              const float* __restrict__ params, float* __restrict__ outm) {
    int r = blockIdx.x * 8 + (threadIdx.x >> 5);
    int t = threadIdx.x & 31;
    if (r < NPOS) {
        float mom   = params[3];
        float cnt   = g_counts[r];
        float valid = (cnt > 0.1f ? 1.0f : 0.0f) * g_vis[r];
        float msc   = valid * mom + 1.0f - valid;
        float gsc   = (1.0f - mom) * valid;
        float denom = cnt + 1e-8f;
        float v0 = memory[(size_t)r * DIM + t]      * msc + (g_get[r * DIM + t]      / denom) * gsc;
        float v1 = memory[(size_t)r * DIM + t + 32] * msc + (g_get[r * DIM + t + 32] / denom) * gsc;
        float ss = v0 * v0 + v1 * v1;
#pragma unroll
        for (int o = 16; o; o >>= 1) ss += __shfl_xor_sync(0xffffffffu, ss, o);
        float inv = 1.0f / fmaxf(sqrtf(ss), 1e-12f);
        outm[(size_t)r * DIM + t]      = v0 * inv;
        outm[(size_t)r * DIM + t + 32] = v1 * inv;
    } else if (r >= NPOS + LRUC * NNEG && r < NPOS + LRUC * NNEG + NNEG) {
        int xs = NPOS + (r - (NPOS + LRUC * NNEG));
        outm[(size_t)r * DIM + t]      = x[(size_t)xs * DIM + t];
        outm[(size_t)r * DIM + t + 32] = x[(size_t)xs * DIM + t + 32];
    } else {
        outm[(size_t)r * DIM + t]      = memory[(size_t)r * DIM + t];
        outm[(size_t)r * DIM + t + 32] = memory[(size_t)r * DIM + t + 32];
    }
}

// ---------------- launch ----------------
extern "C" void kernel_launch(void* const* d_in, const int* in_sizes, int n_in,
                              void* d_out, int out_size) {
    const float* x = nullptr;
    const int*   y = nullptr;
    const int*   visible = nullptr;
    const float* memory = nullptr;
    const float* params = nullptr;
    for (int i = 0; i < n_in; i++) {
        switch (in_sizes[i]) {
            case XROWS * DIM: x = (const float*)d_in[i]; break;
            case NPOS:        y = (const int*)d_in[i]; break;
            case NPOS / 2:    visible = (const int*)d_in[i]; break;
            case MROWS * DIM: memory = (const float*)d_in[i]; break;
            case 4:           params = (const float*)d_in[i]; break;
            default: break;
        }
    }

    float* sim     = (float*)d_out;
    float* out_y   = sim + (size_t)NPOS * SIMCOLS;
    float* out_mem = out_y + NPOS;

    const int SMEM_TOTAL = 49152 + 512;   // A(32K) + B(16K) + ys
    cudaFuncSetAttribute(gemm_mma, cudaFuncAttributeMaxDynamicSharedMemorySize, SMEM_TOTAL);

    split_kernel<<<2048, 256>>>(x, memory);
    gemm_mma<<<dim3(SIMCOLS / BN, NPOS / BM), THREADS, SMEM_TOTAL>>>(y, sim);
    segsum_kernel<<<NPOS / 4, 256>>>(x, visible, out_y);
    update_kernel<<<MROWS / 8, 256>>>(x, memory, params, out_mem);
}